// round 2
// baseline (speedup 1.0000x reference)
#include <cuda_runtime.h>

#define NN 50000
#define EE 800000

// ---------------- scratch (device globals — allocation-free) ----------------
__device__ float    g_q[NN * 128];
__device__ float    g_logits[EE * 8];
__device__ unsigned g_mx[NN * 8];
__device__ float    g_den[NN * 8];
__device__ float    g_aggr[NN * 128];
__device__ int      g_src[EE];
__device__ int      g_dst[EE];
__device__ int      g_is64;   // 1 if edge_index is int64, 0 if int32

// ordered-uint encoding of float for atomicMax
__device__ __forceinline__ unsigned fenc(float f) {
    unsigned u = __float_as_uint(f);
    return (u & 0x80000000u) ? ~u : (u | 0x80000000u);
}
__device__ __forceinline__ float fdec(unsigned u) {
    unsigned v = (u & 0x80000000u) ? (u & 0x7fffffffu) : ~u;
    return __uint_as_float(v);
}

// ---- edge_index dtype detection: int64 LE => odd int32 words all zero ----
__global__ void detect_idx_kernel(const unsigned* __restrict__ raw) {
    if (threadIdx.x == 0 && blockIdx.x == 0) {
        int all_zero = 1;
        for (int i = 1; i < 128; i += 2)
            if (raw[i] != 0u) { all_zero = 0; break; }
        g_is64 = all_zero;
    }
}

__global__ void convert_idx_kernel(const void* __restrict__ raw) {
    int e = blockIdx.x * blockDim.x + threadIdx.x;
    if (e >= EE) return;
    if (g_is64) {
        const long long* p = (const long long*)raw;
        g_src[e] = (int)p[e];
        g_dst[e] = (int)p[EE + e];
    } else {
        const int* p = (const int*)raw;
        g_src[e] = p[e];
        g_dst[e] = p[EE + e];
    }
}

__global__ void init_kernel() {
    int i = blockIdx.x * blockDim.x + threadIdx.x;
    if (i < NN * 8) { g_mx[i] = 0u; g_den[i] = 0.f; }
    if (i < NN * 128) g_aggr[i] = 0.f;
}

// ---------------------------------------------------------------------------
// Fused MLP: X @ W1 + b1 -> LayerNorm(g,be) -> ReLU -> @ W2 + b2 -> epilogue
// EPI 0: rows = nodes, X = h,                 out -> g_q
// EPI 1: rows = edges, X = [ef|h[dst]|h[src]], epilogue: logits + atomicMax
// EPI 2: rows = edges, X = [ef|h[dst]|h[src]], epilogue: alpha*e_w*v scatter
// EPI 3: rows = nodes, X = [g_aggr | h],       out -> outp (d_out)
// Tile: 64 rows x 128 cols, 256 threads, each thread owns 4 rows x 8 cols.
// ---------------------------------------------------------------------------
template <int DIN, int EPI>
__global__ void __launch_bounds__(256)
fused_mlp(const float* __restrict__ ef,
          const float* __restrict__ hh,
          const float* __restrict__ ew,
          const float* __restrict__ W1, const float* __restrict__ B1,
          const float* __restrict__ G,  const float* __restrict__ BE,
          const float* __restrict__ W2, const float* __restrict__ B2,
          float* __restrict__ outp, int nrows)
{
    __shared__ float As[64 * 20];   // [64][16] + pad 4 (keeps 16B alignment)
    __shared__ float Bs[16 * 128];
    __shared__ float Hs[64 * 128];
    __shared__ int   ds[64];
    __shared__ int   ss[64];

    const int tid   = threadIdx.x;
    const int tx    = tid & 15;       // column group (8 cols)
    const int ty    = tid >> 4;       // row group (4 rows)
    const int row0  = blockIdx.x * 64;
    const int myrow = ty * 4;
    const int mycol = tx * 8;
    const int lrow  = tid >> 2;       // A-tile load row 0..63
    const int lq    = (tid & 3) * 4;  // A-tile load col (float4)

    if constexpr (EPI == 1 || EPI == 2) {
        if (tid < 64) {
            int r = row0 + tid;
            ss[tid] = g_src[r];
            ds[tid] = g_dst[r];
        }
        __syncthreads();
    }

    float acc[4][8];
#pragma unroll
    for (int i = 0; i < 4; i++)
#pragma unroll
        for (int j = 0; j < 8; j++) acc[i][j] = 0.f;

    // ---------------- GEMM1: hidden = X @ W1 ----------------
#pragma unroll 1
    for (int k0 = 0; k0 < DIN; k0 += 16) {
        {   // gathered A tile [64][16]
            int r = row0 + lrow;
            if (r >= nrows) r = nrows - 1;
            const float* src;
            if constexpr (EPI == 0) {
                src = hh + (size_t)r * 128 + k0;
            } else if constexpr (EPI == 3) {
                src = (k0 < 128) ? (g_aggr + (size_t)r * 128 + k0)
                                 : (hh + (size_t)r * 128 + (k0 - 128));
            } else {
                if (k0 < 64)        src = ef + (size_t)r * 64 + k0;
                else if (k0 < 192)  src = hh + (size_t)ds[lrow] * 128 + (k0 - 64);
                else                src = hh + (size_t)ss[lrow] * 128 + (k0 - 192);
            }
            *(float4*)(As + lrow * 20 + lq) = *(const float4*)(src + lq);
        }
        {   // W1 chunk [16][128]
            int wr = tid >> 4;
            int wc = (tid & 15) * 8;
            const float* src = W1 + (size_t)(k0 + wr) * 128 + wc;
            *(float4*)(Bs + wr * 128 + wc)     = *(const float4*)(src);
            *(float4*)(Bs + wr * 128 + wc + 4) = *(const float4*)(src + 4);
        }
        __syncthreads();
#pragma unroll
        for (int k = 0; k < 16; k++) {
            float a0 = As[(myrow + 0) * 20 + k];
            float a1 = As[(myrow + 1) * 20 + k];
            float a2 = As[(myrow + 2) * 20 + k];
            float a3 = As[(myrow + 3) * 20 + k];
            float4 b0 = *(float4*)(Bs + k * 128 + mycol);
            float4 b1 = *(float4*)(Bs + k * 128 + mycol + 4);
            float b[8] = {b0.x, b0.y, b0.z, b0.w, b1.x, b1.y, b1.z, b1.w};
#pragma unroll
            for (int j = 0; j < 8; j++) {
                acc[0][j] += a0 * b[j];
                acc[1][j] += a1 * b[j];
                acc[2][j] += a2 * b[j];
                acc[3][j] += a3 * b[j];
            }
        }
        __syncthreads();
    }

    // ---------------- bias + LayerNorm + ReLU -> Hs ----------------
    float gv[8], bev[8], b1v[8];
#pragma unroll
    for (int j = 0; j < 8; j++) {
        gv[j] = G[mycol + j]; bev[j] = BE[mycol + j]; b1v[j] = B1[mycol + j];
    }
#pragma unroll
    for (int i = 0; i < 4; i++) {
        float s = 0.f;
#pragma unroll
        for (int j = 0; j < 8; j++) { acc[i][j] += b1v[j]; s += acc[i][j]; }
        s += __shfl_xor_sync(0xffffffffu, s, 1);
        s += __shfl_xor_sync(0xffffffffu, s, 2);
        s += __shfl_xor_sync(0xffffffffu, s, 4);
        s += __shfl_xor_sync(0xffffffffu, s, 8);
        float mu = s * 0.0078125f;  // /128
        float s2 = 0.f;
#pragma unroll
        for (int j = 0; j < 8; j++) { float d = acc[i][j] - mu; s2 += d * d; }
        s2 += __shfl_xor_sync(0xffffffffu, s2, 1);
        s2 += __shfl_xor_sync(0xffffffffu, s2, 2);
        s2 += __shfl_xor_sync(0xffffffffu, s2, 4);
        s2 += __shfl_xor_sync(0xffffffffu, s2, 8);
        float rs = rsqrtf(s2 * 0.0078125f + 1e-5f);
#pragma unroll
        for (int j = 0; j < 8; j++) {
            float v = (acc[i][j] - mu) * rs * gv[j] + bev[j];
            Hs[(myrow + i) * 128 + mycol + j] = fmaxf(v, 0.f);
        }
    }
    __syncthreads();

    // ---------------- GEMM2: out = Hs @ W2 ----------------
    float ac2[4][8];
#pragma unroll
    for (int i = 0; i < 4; i++)
#pragma unroll
        for (int j = 0; j < 8; j++) ac2[i][j] = 0.f;

#pragma unroll 1
    for (int k0 = 0; k0 < 128; k0 += 16) {
        {
            int wr = tid >> 4;
            int wc = (tid & 15) * 8;
            const float* src = W2 + (size_t)(k0 + wr) * 128 + wc;
            *(float4*)(Bs + wr * 128 + wc)     = *(const float4*)(src);
            *(float4*)(Bs + wr * 128 + wc + 4) = *(const float4*)(src + 4);
        }
        __syncthreads();
#pragma unroll
        for (int k = 0; k < 16; k++) {
            float a0 = Hs[(myrow + 0) * 128 + k0 + k];
            float a1 = Hs[(myrow + 1) * 128 + k0 + k];
            float a2 = Hs[(myrow + 2) * 128 + k0 + k];
            float a3 = Hs[(myrow + 3) * 128 + k0 + k];
            float4 b0 = *(float4*)(Bs + k * 128 + mycol);
            float4 b1 = *(float4*)(Bs + k * 128 + mycol + 4);
            float b[8] = {b0.x, b0.y, b0.z, b0.w, b1.x, b1.y, b1.z, b1.w};
#pragma unroll
            for (int j = 0; j < 8; j++) {
                ac2[0][j] += a0 * b[j];
                ac2[1][j] += a1 * b[j];
                ac2[2][j] += a2 * b[j];
                ac2[3][j] += a3 * b[j];
            }
        }
        __syncthreads();
    }
#pragma unroll
    for (int j = 0; j < 8; j++) {
        float b2v = B2[mycol + j];
#pragma unroll
        for (int i = 0; i < 4; i++) ac2[i][j] += b2v;
    }

    // ---------------- epilogues ----------------
    if constexpr (EPI == 0) {
#pragma unroll
        for (int i = 0; i < 4; i++) {
            int r = row0 + myrow + i;
            if (r < nrows) {
                *(float4*)(g_q + (size_t)r * 128 + mycol) =
                    make_float4(ac2[i][0], ac2[i][1], ac2[i][2], ac2[i][3]);
                *(float4*)(g_q + (size_t)r * 128 + mycol + 4) =
                    make_float4(ac2[i][4], ac2[i][5], ac2[i][6], ac2[i][7]);
            }
        }
    } else if constexpr (EPI == 3) {
#pragma unroll
        for (int i = 0; i < 4; i++) {
            int r = row0 + myrow + i;
            if (r < nrows) {
                *(float4*)(outp + (size_t)r * 128 + mycol) =
                    make_float4(ac2[i][0], ac2[i][1], ac2[i][2], ac2[i][3]);
                *(float4*)(outp + (size_t)r * 128 + mycol + 4) =
                    make_float4(ac2[i][4], ac2[i][5], ac2[i][6], ac2[i][7]);
            }
        }
    } else if constexpr (EPI == 1) {
        // logits: per-head dot(q[dst], k) / sqrt(16)
#pragma unroll
        for (int i = 0; i < 4; i++) {
            int r = row0 + myrow + i;
            int d = ds[myrow + i];
            const float* qp = g_q + (size_t)d * 128 + mycol;
            float4 q0 = *(const float4*)qp;
            float4 q1 = *(const float4*)(qp + 4);
            float p = ac2[i][0] * q0.x + ac2[i][1] * q0.y + ac2[i][2] * q0.z + ac2[i][3] * q0.w
                    + ac2[i][4] * q1.x + ac2[i][5] * q1.y + ac2[i][6] * q1.z + ac2[i][7] * q1.w;
            p += __shfl_xor_sync(0xffffffffu, p, 1);  // pair covers one 16-wide head
            if ((tx & 1) == 0) {
                int hd = tx >> 1;
                float lg = p * 0.25f;
                g_logits[(size_t)r * 8 + hd] = lg;
                atomicMax(&g_mx[d * 8 + hd], fenc(lg));
            }
        }
    } else {  // EPI == 2: alpha * e_w * v  scattered into g_aggr
#pragma unroll
        for (int i = 0; i < 4; i++) {
            int r = row0 + myrow + i;
            int d = ds[myrow + i];
            int hd = tx >> 1;  // 8 cols of one head per thread
            float lg = g_logits[(size_t)r * 8 + hd];
            float mx = fdec(g_mx[d * 8 + hd]);
            float dn = g_den[d * 8 + hd];
            float s = __expf(lg - mx) / dn * ew[r];
            float* op = g_aggr + (size_t)d * 128 + mycol;
            asm volatile("red.global.add.v4.f32 [%0], {%1,%2,%3,%4};" ::
                "l"(op), "f"(ac2[i][0] * s), "f"(ac2[i][1] * s),
                         "f"(ac2[i][2] * s), "f"(ac2[i][3] * s) : "memory");
            asm volatile("red.global.add.v4.f32 [%0], {%1,%2,%3,%4};" ::
                "l"(op + 4), "f"(ac2[i][4] * s), "f"(ac2[i][5] * s),
                             "f"(ac2[i][6] * s), "f"(ac2[i][7] * s) : "memory");
        }
    }
}

// softmax denominator: den[dst,h] += exp(logit - mx[dst,h])
__global__ void den_kernel() {
    int i = blockIdx.x * blockDim.x + threadIdx.x;
    if (i >= EE * 8) return;
    int e = i >> 3, hd = i & 7;
    int d = g_dst[e];
    float lg = g_logits[i];
    float mx = fdec(g_mx[d * 8 + hd]);
    atomicAdd(&g_den[d * 8 + hd], __expf(lg - mx));
}

extern "C" void kernel_launch(void* const* d_in, const int* in_sizes, int n_in,
                              void* d_out, int out_size)
{
    const float* hPtr = (const float*)d_in[0];
    const float* ef   = (const float*)d_in[1];
    const float* ew   = (const float*)d_in[2];
    const void*  eidx = (const void*)d_in[3];
    const float* hk[6], *hv[6], *hq[6], *no[6];
    for (int i = 0; i < 6; i++) {
        hk[i] = (const float*)d_in[4 + i];
        hv[i] = (const float*)d_in[10 + i];
        hq[i] = (const float*)d_in[16 + i];
        no[i] = (const float*)d_in[22 + i];
    }
    float* outp = (float*)d_out;

    const int nodeBlocks = (NN + 63) / 64;          // 782
    const int edgeBlocks = EE / 64;                 // 12500
    const int flatBlocks = (NN * 128 + 255) / 256;  // 25000 (covers all init)
    const int denBlocks  = (EE * 8 + 255) / 256;    // 25000
    const int idxBlocks  = (EE + 255) / 256;

    // 0) detect edge_index dtype and convert to int32 scratch
    detect_idx_kernel<<<1, 32>>>((const unsigned*)eidx);
    convert_idx_kernel<<<idxBlocks, 256>>>(eidx);

    // 1) zero scratch
    init_kernel<<<flatBlocks, 256>>>();

    // 2) q = MLP_hq(h)
    fused_mlp<128, 0><<<nodeBlocks, 256>>>(
        nullptr, hPtr, nullptr,
        hq[0], hq[1], hq[2], hq[3], hq[4], hq[5], nullptr, NN);

    // 3) k = MLP_hk(kv); logits + per-node max
    fused_mlp<320, 1><<<edgeBlocks, 256>>>(
        ef, hPtr, nullptr,
        hk[0], hk[1], hk[2], hk[3], hk[4], hk[5], nullptr, EE);

    // 4) softmax denominators
    den_kernel<<<denBlocks, 256>>>();

    // 5) v = MLP_hv(kv); scatter alpha * e_w * v into g_aggr
    fused_mlp<320, 2><<<edgeBlocks, 256>>>(
        ef, hPtr, ew,
        hv[0], hv[1], hv[2], hv[3], hv[4], hv[5], nullptr, EE);

    // 6) out = MLP_no([aggr | h])
    fused_mlp<256, 3><<<nodeBlocks, 256>>>(
        nullptr, hPtr, nullptr,
        no[0], no[1], no[2], no[3], no[4], no[5], outp, NN);
}

// round 3
// speedup vs baseline: 1.4670x; 1.4670x over previous
#include <cuda_runtime.h>

#define NN 50000
#define EE 800000

// ---------------- scratch (device globals — allocation-free) ----------------
__device__ float    g_q[NN * 128];
__device__ float    g_logits[EE * 8];
__device__ unsigned g_mx[NN * 8];
__device__ float    g_den[NN * 8];
__device__ float    g_aggr[NN * 128];
__device__ int      g_src[EE];
__device__ int      g_dst[EE];
__device__ int      g_is64;

__device__ __forceinline__ unsigned fenc(float f) {
    unsigned u = __float_as_uint(f);
    return (u & 0x80000000u) ? ~u : (u | 0x80000000u);
}
__device__ __forceinline__ float fdec(unsigned u) {
    unsigned v = (u & 0x80000000u) ? (u & 0x7fffffffu) : ~u;
    return __uint_as_float(v);
}

__global__ void detect_idx_kernel(const unsigned* __restrict__ raw) {
    if (threadIdx.x == 0 && blockIdx.x == 0) {
        int all_zero = 1;
        for (int i = 1; i < 128; i += 2)
            if (raw[i] != 0u) { all_zero = 0; break; }
        g_is64 = all_zero;
    }
}

__global__ void convert_idx_kernel(const void* __restrict__ raw) {
    int e = blockIdx.x * blockDim.x + threadIdx.x;
    if (e >= EE) return;
    if (g_is64) {
        const long long* p = (const long long*)raw;
        g_src[e] = (int)p[e];
        g_dst[e] = (int)p[EE + e];
    } else {
        const int* p = (const int*)raw;
        g_src[e] = p[e];
        g_dst[e] = p[EE + e];
    }
}

__global__ void init_kernel() {
    int i = blockIdx.x * blockDim.x + threadIdx.x;
    if (i < NN * 8) { g_mx[i] = 0u; g_den[i] = 0.f; }
    if (i < NN * 128) g_aggr[i] = 0.f;
}

// ---------------------------------------------------------------------------
// Fused MLP, CTA tile 128 rows x 128 cols, 256 threads, 8x8 per thread.
// GEMM1 A-tile staged k-major in smem (vector reads with broadcast).
// EPI 0: nodes, X=h                 -> g_q
// EPI 1: edges, X=[ef|h[dst]|h[src]] -> logits + atomicMax
// EPI 2: edges, X=[ef|h[dst]|h[src]] -> alpha*e_w*v scatter
// EPI 3: nodes, X=[g_aggr|h]         -> outp
// ---------------------------------------------------------------------------
#define HSTR 132   // Hs row stride (floats)

template <int DIN, int EPI>
__global__ void __launch_bounds__(256, 2)
fused_mlp(const float* __restrict__ ef,
          const float* __restrict__ hh,
          const float* __restrict__ ew,
          const float* __restrict__ W1, const float* __restrict__ B1,
          const float* __restrict__ G,  const float* __restrict__ BE,
          const float* __restrict__ W2, const float* __restrict__ B2,
          float* __restrict__ outp, int nrows)
{
    extern __shared__ float sm[];
    float* As = sm;                       // [16][128]  k-major
    float* Bs = sm + 16 * 128;            // [16][128]
    float* Hs = sm + 32 * 128;            // [128][HSTR] row-major
    int*   ds = (int*)(sm + 32 * 128 + 128 * HSTR);
    int*   ss = ds + 128;

    const int tid   = threadIdx.x;
    const int tx    = tid & 15;
    const int ty    = tid >> 4;
    const int row0  = blockIdx.x * 128;
    const int myrow = ty * 8;
    const int mycol = tx * 8;
    const int rowL  = tid & 127;          // loader row
    const int kL    = (tid >> 7) * 8;     // loader k-offset within chunk (0 or 8)

    if constexpr (EPI == 1 || EPI == 2) {
        if (tid < 128) {
            int r = row0 + tid;
            ss[tid] = g_src[r];
            ds[tid] = g_dst[r];
        }
    }
    __syncthreads();

    // clamped row for loads
    int rL = row0 + rowL;
    if (rL >= nrows) rL = nrows - 1;

    // A source pointer for current chunk
    auto a_ptr = [&](int k0) -> const float* {
        int kk = k0 + kL;
        if constexpr (EPI == 0) {
            return hh + (size_t)rL * 128 + kk;
        } else if constexpr (EPI == 3) {
            return (kk < 128) ? (g_aggr + (size_t)rL * 128 + kk)
                              : (hh + (size_t)rL * 128 + (kk - 128));
        } else {
            if (kk < 64)       return ef + (size_t)rL * 64 + kk;
            else if (kk < 192) return hh + (size_t)ds[rowL] * 128 + (kk - 64);
            else               return hh + (size_t)ss[rowL] * 128 + (kk - 192);
        }
    };

    float acc[8][8];
#pragma unroll
    for (int i = 0; i < 8; i++)
#pragma unroll
        for (int j = 0; j < 8; j++) acc[i][j] = 0.f;

    // prefetch chunk 0
    float4 pa0 = *(const float4*)(a_ptr(0));
    float4 pa1 = *(const float4*)(a_ptr(0) + 4);
    const float* wsrc = W1 + (size_t)ty * 128 + mycol;
    float4 pb0 = *(const float4*)(wsrc);
    float4 pb1 = *(const float4*)(wsrc + 4);

    // ---------------- GEMM1 ----------------
#pragma unroll 1
    for (int k0 = 0; k0 < DIN; k0 += 16) {
        // store staged regs -> smem (A transposed to k-major)
        As[(kL + 0) * 128 + rowL] = pa0.x;
        As[(kL + 1) * 128 + rowL] = pa0.y;
        As[(kL + 2) * 128 + rowL] = pa0.z;
        As[(kL + 3) * 128 + rowL] = pa0.w;
        As[(kL + 4) * 128 + rowL] = pa1.x;
        As[(kL + 5) * 128 + rowL] = pa1.y;
        As[(kL + 6) * 128 + rowL] = pa1.z;
        As[(kL + 7) * 128 + rowL] = pa1.w;
        *(float4*)(Bs + ty * 128 + mycol)     = pb0;
        *(float4*)(Bs + ty * 128 + mycol + 4) = pb1;
        __syncthreads();

        if (k0 + 16 < DIN) {   // prefetch next chunk
            pa0 = *(const float4*)(a_ptr(k0 + 16));
            pa1 = *(const float4*)(a_ptr(k0 + 16) + 4);
            const float* ws = W1 + (size_t)(k0 + 16 + ty) * 128 + mycol;
            pb0 = *(const float4*)(ws);
            pb1 = *(const float4*)(ws + 4);
        }

#pragma unroll
        for (int k = 0; k < 16; k++) {
            float4 a0 = *(float4*)(As + k * 128 + myrow);
            float4 a1 = *(float4*)(As + k * 128 + myrow + 4);
            float4 b0 = *(float4*)(Bs + k * 128 + mycol);
            float4 b1 = *(float4*)(Bs + k * 128 + mycol + 4);
            float a[8] = {a0.x, a0.y, a0.z, a0.w, a1.x, a1.y, a1.z, a1.w};
            float b[8] = {b0.x, b0.y, b0.z, b0.w, b1.x, b1.y, b1.z, b1.w};
#pragma unroll
            for (int i = 0; i < 8; i++)
#pragma unroll
                for (int j = 0; j < 8; j++)
                    acc[i][j] += a[i] * b[j];
        }
        __syncthreads();
    }

    // ---------------- bias + LayerNorm + ReLU -> Hs ----------------
    {
        float gv[8], bev[8], b1v[8];
#pragma unroll
        for (int j = 0; j < 8; j++) {
            gv[j] = G[mycol + j]; bev[j] = BE[mycol + j]; b1v[j] = B1[mycol + j];
        }
#pragma unroll
        for (int i = 0; i < 8; i++) {
            float s = 0.f;
#pragma unroll
            for (int j = 0; j < 8; j++) { acc[i][j] += b1v[j]; s += acc[i][j]; }
            s += __shfl_xor_sync(0xffffffffu, s, 1);
            s += __shfl_xor_sync(0xffffffffu, s, 2);
            s += __shfl_xor_sync(0xffffffffu, s, 4);
            s += __shfl_xor_sync(0xffffffffu, s, 8);
            float mu = s * 0.0078125f;
            float s2 = 0.f;
#pragma unroll
            for (int j = 0; j < 8; j++) { float d = acc[i][j] - mu; s2 += d * d; }
            s2 += __shfl_xor_sync(0xffffffffu, s2, 1);
            s2 += __shfl_xor_sync(0xffffffffu, s2, 2);
            s2 += __shfl_xor_sync(0xffffffffu, s2, 4);
            s2 += __shfl_xor_sync(0xffffffffu, s2, 8);
            float rs = rsqrtf(s2 * 0.0078125f + 1e-5f);
            float4 h0, h1;
            h0.x = fmaxf((acc[i][0] - mu) * rs * gv[0] + bev[0], 0.f);
            h0.y = fmaxf((acc[i][1] - mu) * rs * gv[1] + bev[1], 0.f);
            h0.z = fmaxf((acc[i][2] - mu) * rs * gv[2] + bev[2], 0.f);
            h0.w = fmaxf((acc[i][3] - mu) * rs * gv[3] + bev[3], 0.f);
            h1.x = fmaxf((acc[i][4] - mu) * rs * gv[4] + bev[4], 0.f);
            h1.y = fmaxf((acc[i][5] - mu) * rs * gv[5] + bev[5], 0.f);
            h1.z = fmaxf((acc[i][6] - mu) * rs * gv[6] + bev[6], 0.f);
            h1.w = fmaxf((acc[i][7] - mu) * rs * gv[7] + bev[7], 0.f);
            *(float4*)(Hs + (myrow + i) * HSTR + mycol)     = h0;
            *(float4*)(Hs + (myrow + i) * HSTR + mycol + 4) = h1;
        }
    }
    __syncthreads();

    // ---------------- GEMM2: out = Hs @ W2 ----------------
    float ac2[8][8];
#pragma unroll
    for (int i = 0; i < 8; i++)
#pragma unroll
        for (int j = 0; j < 8; j++) ac2[i][j] = 0.f;

    {
        const float* ws = W2 + (size_t)ty * 128 + mycol;
        pb0 = *(const float4*)(ws);
        pb1 = *(const float4*)(ws + 4);
    }
#pragma unroll 1
    for (int k0 = 0; k0 < 128; k0 += 16) {
        *(float4*)(Bs + ty * 128 + mycol)     = pb0;
        *(float4*)(Bs + ty * 128 + mycol + 4) = pb1;
        __syncthreads();
        if (k0 + 16 < 128) {
            const float* ws = W2 + (size_t)(k0 + 16 + ty) * 128 + mycol;
            pb0 = *(const float4*)(ws);
            pb1 = *(const float4*)(ws + 4);
        }
#pragma unroll
        for (int kb = 0; kb < 16; kb += 2) {
            float2 av[8];
#pragma unroll
            for (int i = 0; i < 8; i++)
                av[i] = *(float2*)(Hs + (myrow + i) * HSTR + k0 + kb);
#pragma unroll
            for (int kk = 0; kk < 2; kk++) {
                int k = kb + kk;
                float4 b0 = *(float4*)(Bs + k * 128 + mycol);
                float4 b1 = *(float4*)(Bs + k * 128 + mycol + 4);
                float b[8] = {b0.x, b0.y, b0.z, b0.w, b1.x, b1.y, b1.z, b1.w};
#pragma unroll
                for (int i = 0; i < 8; i++) {
                    float a = kk ? av[i].y : av[i].x;
#pragma unroll
                    for (int j = 0; j < 8; j++)
                        ac2[i][j] += a * b[j];
                }
            }
        }
        __syncthreads();
    }
#pragma unroll
    for (int j = 0; j < 8; j++) {
        float b2v = B2[mycol + j];
#pragma unroll
        for (int i = 0; i < 8; i++) ac2[i][j] += b2v;
    }

    // ---------------- epilogues ----------------
    if constexpr (EPI == 0 || EPI == 3) {
        float* dst0 = (EPI == 0) ? g_q : outp;
#pragma unroll
        for (int i = 0; i < 8; i++) {
            int r = row0 + myrow + i;
            if (r < nrows) {
                *(float4*)(dst0 + (size_t)r * 128 + mycol) =
                    make_float4(ac2[i][0], ac2[i][1], ac2[i][2], ac2[i][3]);
                *(float4*)(dst0 + (size_t)r * 128 + mycol + 4) =
                    make_float4(ac2[i][4], ac2[i][5], ac2[i][6], ac2[i][7]);
            }
        }
    } else if constexpr (EPI == 1) {
#pragma unroll
        for (int i = 0; i < 8; i++) {
            int r = row0 + myrow + i;
            int d = ds[myrow + i];
            const float* qp = g_q + (size_t)d * 128 + mycol;
            float4 q0 = *(const float4*)qp;
            float4 q1 = *(const float4*)(qp + 4);
            float p = ac2[i][0] * q0.x + ac2[i][1] * q0.y + ac2[i][2] * q0.z + ac2[i][3] * q0.w
                    + ac2[i][4] * q1.x + ac2[i][5] * q1.y + ac2[i][6] * q1.z + ac2[i][7] * q1.w;
            p += __shfl_xor_sync(0xffffffffu, p, 1);
            if ((tx & 1) == 0) {
                int hd = tx >> 1;
                float lg = p * 0.25f;
                g_logits[(size_t)r * 8 + hd] = lg;
                atomicMax(&g_mx[d * 8 + hd], fenc(lg));
            }
        }
    } else {  // EPI == 2
#pragma unroll
        for (int i = 0; i < 8; i++) {
            int r = row0 + myrow + i;
            int d = ds[myrow + i];
            int hd = tx >> 1;
            float lg = g_logits[(size_t)r * 8 + hd];
            float mx = fdec(g_mx[d * 8 + hd]);
            float dn = g_den[d * 8 + hd];
            float s = __expf(lg - mx) / dn * ew[r];
            float* op = g_aggr + (size_t)d * 128 + mycol;
            asm volatile("red.global.add.v4.f32 [%0], {%1,%2,%3,%4};" ::
                "l"(op), "f"(ac2[i][0] * s), "f"(ac2[i][1] * s),
                         "f"(ac2[i][2] * s), "f"(ac2[i][3] * s) : "memory");
            asm volatile("red.global.add.v4.f32 [%0], {%1,%2,%3,%4};" ::
                "l"(op + 4), "f"(ac2[i][4] * s), "f"(ac2[i][5] * s),
                             "f"(ac2[i][6] * s), "f"(ac2[i][7] * s) : "memory");
        }
    }
}

__global__ void den_kernel() {
    int i = blockIdx.x * blockDim.x + threadIdx.x;
    if (i >= EE * 8) return;
    int e = i >> 3, hd = i & 7;
    int d = g_dst[e];
    float lg = g_logits[i];
    float mx = fdec(g_mx[d * 8 + hd]);
    atomicAdd(&g_den[d * 8 + hd], __expf(lg - mx));
}

static const int SMEM_BYTES = (32 * 128 + 128 * HSTR) * 4 + 2 * 128 * 4;

extern "C" void kernel_launch(void* const* d_in, const int* in_sizes, int n_in,
                              void* d_out, int out_size)
{
    const float* hPtr = (const float*)d_in[0];
    const float* ef   = (const float*)d_in[1];
    const float* ew   = (const float*)d_in[2];
    const void*  eidx = (const void*)d_in[3];
    const float* hk[6], *hv[6], *hq[6], *no[6];
    for (int i = 0; i < 6; i++) {
        hk[i] = (const float*)d_in[4 + i];
        hv[i] = (const float*)d_in[10 + i];
        hq[i] = (const float*)d_in[16 + i];
        no[i] = (const float*)d_in[22 + i];
    }
    float* outp = (float*)d_out;

    cudaFuncSetAttribute(fused_mlp<128, 0>, cudaFuncAttributeMaxDynamicSharedMemorySize, SMEM_BYTES);
    cudaFuncSetAttribute(fused_mlp<320, 1>, cudaFuncAttributeMaxDynamicSharedMemorySize, SMEM_BYTES);
    cudaFuncSetAttribute(fused_mlp<320, 2>, cudaFuncAttributeMaxDynamicSharedMemorySize, SMEM_BYTES);
    cudaFuncSetAttribute(fused_mlp<256, 3>, cudaFuncAttributeMaxDynamicSharedMemorySize, SMEM_BYTES);

    const int nodeBlocks = (NN + 127) / 128;        // 391
    const int edgeBlocks = EE / 128;                // 6250
    const int flatBlocks = (NN * 128 + 255) / 256;
    const int denBlocks  = (EE * 8 + 255) / 256;
    const int idxBlocks  = (EE + 255) / 256;

    detect_idx_kernel<<<1, 32>>>((const unsigned*)eidx);
    convert_idx_kernel<<<idxBlocks, 256>>>(eidx);
    init_kernel<<<flatBlocks, 256>>>();

    fused_mlp<128, 0><<<nodeBlocks, 256, SMEM_BYTES>>>(
        nullptr, hPtr, nullptr,
        hq[0], hq[1], hq[2], hq[3], hq[4], hq[5], nullptr, NN);

    fused_mlp<320, 1><<<edgeBlocks, 256, SMEM_BYTES>>>(
        ef, hPtr, nullptr,
        hk[0], hk[1], hk[2], hk[3], hk[4], hk[5], nullptr, EE);

    den_kernel<<<denBlocks, 256>>>();

    fused_mlp<320, 2><<<edgeBlocks, 256, SMEM_BYTES>>>(
        ef, hPtr, ew,
        hv[0], hv[1], hv[2], hv[3], hv[4], hv[5], nullptr, EE);

    fused_mlp<256, 3><<<nodeBlocks, 256, SMEM_BYTES>>>(
        nullptr, hPtr, nullptr,
        no[0], no[1], no[2], no[3], no[4], no[5], outp, NN);
}

// round 5
// speedup vs baseline: 2.7029x; 1.8425x over previous
#include <cuda_runtime.h>
#include <cuda_bf16.h>
#include <cstdint>

#define NN 50000
#define EE 800000

// ---------------- scratch (device globals — allocation-free) ----------------
__device__ float    g_q[NN * 128];
__device__ float    g_logits[EE * 8];
__device__ unsigned g_mx[NN * 8];
__device__ float    g_den[NN * 8];
__device__ float    g_aggr[NN * 128];
__device__ int      g_src[EE];
__device__ int      g_dst[EE];
__device__ int      g_is64;
// pre-split, pre-swizzled weight tiles: [mlp 0=hk,1=hv][tile 0..6][hi,lo] 16KB each
__device__ char     g_wt[2 * 7 * 2 * 16384];
// pre-split inputs (bf16 hi / lo), 16B-aligned
__device__ uint4    g_efh[EE * 64 / 8];
__device__ uint4    g_efl[EE * 64 / 8];
__device__ uint4    g_hh[NN * 128 / 8];
__device__ uint4    g_hl[NN * 128 / 8];

__device__ __forceinline__ unsigned fenc(float f) {
    unsigned u = __float_as_uint(f);
    return (u & 0x80000000u) ? ~u : (u | 0x80000000u);
}
__device__ __forceinline__ float fdec(unsigned u) {
    unsigned v = (u & 0x80000000u) ? (u & 0x7fffffffu) : ~u;
    return __uint_as_float(v);
}

// ======================= PTX helpers (base-target safe) =======================
__device__ __forceinline__ uint32_t smem_u32(const void* p) {
    uint32_t a;
    asm("{ .reg .u64 t; cvta.to.shared.u64 t, %1; cvt.u32.u64 %0, t; }" : "=r"(a) : "l"(p));
    return a;
}
__device__ __forceinline__ void cpa16(uint32_t dst, const void* src) {
    asm volatile("cp.async.cg.shared.global [%0], [%1], 16;" :: "r"(dst), "l"(src) : "memory");
}
#define CPA_COMMIT() asm volatile("cp.async.commit_group;" ::: "memory")
#define CPA_WAIT(n)  asm volatile("cp.async.wait_group %0;" :: "n"(n) : "memory")

__device__ __forceinline__ void ldsm4(uint32_t* r, uint32_t addr) {
    asm volatile("ldmatrix.sync.aligned.m8n8.x4.shared.b16 {%0,%1,%2,%3}, [%4];"
                 : "=r"(r[0]), "=r"(r[1]), "=r"(r[2]), "=r"(r[3]) : "r"(addr));
}
__device__ __forceinline__ void mma_bf16(float* c, const uint32_t* a, uint32_t b0, uint32_t b1) {
    asm volatile("mma.sync.aligned.m16n8k16.row.col.f32.bf16.bf16.f32 "
                 "{%0,%1,%2,%3}, {%4,%5,%6,%7}, {%8,%9}, {%0,%1,%2,%3};"
                 : "+f"(c[0]), "+f"(c[1]), "+f"(c[2]), "+f"(c[3])
                 : "r"(a[0]), "r"(a[1]), "r"(a[2]), "r"(a[3]), "r"(b0), "r"(b1));
}

#define SW(o) ((o) ^ (((o) >> 3) & 0x70))

__device__ __forceinline__ unsigned pack2(float a, float b) {
    __nv_bfloat162 t = __floats2bfloat162_rn(a, b);
    return *reinterpret_cast<unsigned*>(&t);
}
__device__ __forceinline__ void split8(const float* x, uint4& hi, uint4& lo) {
    float h[8], l[8];
#pragma unroll
    for (int i = 0; i < 8; i++) {
        __nv_bfloat16 b = __float2bfloat16(x[i]);
        h[i] = __bfloat162float(b);
        l[i] = x[i] - h[i];
    }
    hi = make_uint4(pack2(h[0], h[1]), pack2(h[2], h[3]), pack2(h[4], h[5]), pack2(h[6], h[7]));
    lo = make_uint4(pack2(l[0], l[1]), pack2(l[2], l[3]), pack2(l[4], l[5]), pack2(l[6], l[7]));
}

// =================== setup kernels ===================
__global__ void detect_idx_kernel(const unsigned* __restrict__ raw) {
    if (threadIdx.x == 0 && blockIdx.x == 0) {
        int all_zero = 1;
        for (int i = 1; i < 128; i += 2)
            if (raw[i] != 0u) { all_zero = 0; break; }
        g_is64 = all_zero;
    }
}
__global__ void convert_idx_kernel(const void* __restrict__ raw) {
    int e = blockIdx.x * blockDim.x + threadIdx.x;
    if (e >= EE) return;
    if (g_is64) {
        const long long* p = (const long long*)raw;
        g_src[e] = (int)p[e];  g_dst[e] = (int)p[EE + e];
    } else {
        const int* p = (const int*)raw;
        g_src[e] = p[e];  g_dst[e] = p[EE + e];
    }
}
__global__ void init_kernel() {
    int i = blockIdx.x * blockDim.x + threadIdx.x;
    if (i < NN * 8) { g_mx[i] = 0u; g_den[i] = 0.f; }
    if (i < NN * 128) g_aggr[i] = 0.f;
}

// split ef + h into bf16 hi/lo (done once, used by both edge kernels)
__global__ void prep_in(const float* __restrict__ ef, const float* __restrict__ hh) {
    const int totEf = EE * 64 / 8;      // 6.4M
    const int totH  = NN * 128 / 8;     // 800K
    int i = blockIdx.x * blockDim.x + threadIdx.x;
    if (i < totEf) {
        float x[8];
        float4 v0 = *(const float4*)(ef + (size_t)i * 8);
        float4 v1 = *(const float4*)(ef + (size_t)i * 8 + 4);
        x[0]=v0.x; x[1]=v0.y; x[2]=v0.z; x[3]=v0.w; x[4]=v1.x; x[5]=v1.y; x[6]=v1.z; x[7]=v1.w;
        uint4 hi, lo; split8(x, hi, lo);
        g_efh[i] = hi; g_efl[i] = lo;
    } else if (i < totEf + totH) {
        int j = i - totEf;
        float x[8];
        float4 v0 = *(const float4*)(hh + (size_t)j * 8);
        float4 v1 = *(const float4*)(hh + (size_t)j * 8 + 4);
        x[0]=v0.x; x[1]=v0.y; x[2]=v0.z; x[3]=v0.w; x[4]=v1.x; x[5]=v1.y; x[6]=v1.z; x[7]=v1.w;
        uint4 hi, lo; split8(x, hi, lo);
        g_hh[j] = hi; g_hl[j] = lo;
    }
}

// pre-split + pre-swizzle hk/hv weights (transposed to [n][k])
__global__ void prep_w(const float* __restrict__ k1, const float* __restrict__ k2,
                       const float* __restrict__ v1, const float* __restrict__ v2) {
    int idx = blockIdx.x * blockDim.x + threadIdx.x;
    if (idx >= 2 * 7 * 1024) return;
    int m = idx / 7168;
    int rem = idx % 7168;
    int t = rem >> 10;
    int r2 = rem & 1023;
    int n = r2 >> 3, kg = r2 & 7;
    const float* W = (m == 0) ? (t < 5 ? k1 : k2) : (t < 5 ? v1 : v2);
    int k0 = (t < 5) ? t * 64 : (t - 5) * 64;
    float x[8];
#pragma unroll
    for (int j = 0; j < 8; j++)
        x[j] = W[(size_t)(k0 + kg * 8 + j) * 128 + n];
    uint4 hi, lo;
    split8(x, hi, lo);
    size_t slot = (size_t)(m * 7 + t) * 2;
    int off = SW(n * 128 + kg * 16);
    *(uint4*)(g_wt + slot * 16384 + off) = hi;
    *(uint4*)(g_wt + (slot + 1) * 16384 + off) = lo;
}

// ============================================================================
// mma.sync edge MLP: CTA = 128 edges x 128 cols; 8 warps as 4(rows)x2(cols);
// warp = 32 rows x 64 cols. 3-term bf16 split GEMM. K=320 then LN then K=128.
// ============================================================================
#define BUF     65536
#define OFF_PS  (2 * BUF)
#define OFF_PQ  (2 * BUF + 1024)
#define OFF_DS  (2 * BUF + 2048)
#define OFF_SS  (2 * BUF + 2560)
#define EDGE_SMEM (2 * BUF + 3072)

// one 64-k chunk of MMAs: A tile (hi at aBase, lo +16KB), B tile (hi bBase, lo +16KB)
__device__ __forceinline__ void mma_chunk(const char* smc, uint32_t aBase, uint32_t bBase,
                                          int wr, int wc, int lid, float acc[2][8][4]) {
    const int mi  = lid >> 3;
    const int rin = ((mi & 1) << 3) + (lid & 7);
    const int kh  = (mi >> 1) << 4;
    const int nin = ((mi >> 1) << 3) + (lid & 7);
    const int khb = (mi & 1) << 4;
#pragma unroll
    for (int s = 0; s < 4; s++) {
        uint32_t ah[2][4], al[2][4];
#pragma unroll
        for (int mt = 0; mt < 2; mt++) {
            uint32_t off = SW((wr * 32 + mt * 16 + rin) * 128 + s * 32 + kh);
            ldsm4(ah[mt], aBase + off);
            ldsm4(al[mt], aBase + 16384 + off);
        }
#pragma unroll
        for (int p = 0; p < 4; p++) {
            uint32_t boff = SW((wc * 64 + p * 16 + nin) * 128 + s * 32 + khb);
            uint32_t bh4[4], bl4[4];
            ldsm4(bh4, bBase + boff);
            ldsm4(bl4, bBase + 16384 + boff);
#pragma unroll
            for (int mt = 0; mt < 2; mt++)
#pragma unroll
                for (int ntl = 0; ntl < 2; ntl++) {
                    float* C = acc[mt][p * 2 + ntl];
                    mma_bf16(C, ah[mt], bh4[ntl * 2], bh4[ntl * 2 + 1]);
                    mma_bf16(C, al[mt], bh4[ntl * 2], bh4[ntl * 2 + 1]);
                    mma_bf16(C, ah[mt], bl4[ntl * 2], bl4[ntl * 2 + 1]);
                }
        }
    }
}

template <int EPI, int MIDX>
__global__ void __launch_bounds__(256, 1)
edge_mlp(const float* __restrict__ ew,
         const float* __restrict__ B1, const float* __restrict__ G,
         const float* __restrict__ BE, const float* __restrict__ B2)
{
    extern __shared__ char smc[];
    const int tid = threadIdx.x;
    const int lid = tid & 31, wid = tid >> 5;
    const int wr = wid >> 1, wc = wid & 1;
    const int row0 = blockIdx.x * 128;
    uint32_t sbase = smem_u32(smc);
    int*   ds = (int*)(smc + OFF_DS);
    int*   ss = (int*)(smc + OFF_SS);
    float* pS = (float*)(smc + OFF_PS);
    float* pQ = (float*)(smc + OFF_PQ);

    if (tid < 128) { ds[tid] = g_dst[row0 + tid]; ss[tid] = g_src[row0 + tid]; }

    const int arow = tid >> 1;
    const int sel  = tid & 1;     // 0 = hi, 1 = lo

    auto issueA = [&](int c) {
        const char* src;
        if (c == 0)
            src = (const char*)(sel ? g_efl : g_efh) + (size_t)(row0 + arow) * 128;
        else if (c < 3)
            src = (const char*)(sel ? g_hl : g_hh) + (size_t)ds[arow] * 256 + (c - 1) * 128;
        else
            src = (const char*)(sel ? g_hl : g_hh) + (size_t)ss[arow] * 256 + (c - 3) * 128;
        uint32_t ab = sbase + (c & 1) * BUF + sel * 16384;
#pragma unroll
        for (int g = 0; g < 8; g++)
            cpa16(ab + SW(arow * 128 + g * 16), src + g * 16);
    };
    auto issueB = [&](int c) {
        const char* src = g_wt + (size_t)((MIDX * 7 + c) * 2) * 16384;
        uint32_t bb = sbase + (c & 1) * BUF + 32768;
#pragma unroll
        for (int i = 0; i < 8; i++) {
            int ix = (tid + i * 256) * 16;
            cpa16(bb + ix, src + ix);
        }
    };
    auto issueW2 = [&]() {
#pragma unroll
        for (int t = 0; t < 2; t++) {
            const char* src = g_wt + (size_t)((MIDX * 7 + 5 + t) * 2) * 16384;
            uint32_t bb = sbase + BUF + t * 32768;
#pragma unroll
            for (int i = 0; i < 8; i++) {
                int ix = (tid + i * 256) * 16;
                cpa16(bb + ix, src + ix);
            }
        }
    };

    float acc[2][8][4];
#pragma unroll
    for (int a = 0; a < 2; a++)
#pragma unroll
        for (int b = 0; b < 8; b++)
#pragma unroll
            for (int c = 0; c < 4; c++) acc[a][b][c] = 0.f;

    // pipeline: chunk0 (no indices needed), sync for ds/ss, chunk1...
    issueA(0); issueB(0); CPA_COMMIT();
    __syncthreads();
    issueA(1); issueB(1); CPA_COMMIT();

#pragma unroll 1
    for (int c = 0; c < 5; c++) {
        CPA_WAIT(1);
        __syncthreads();
        mma_chunk(smc, sbase + (c & 1) * BUF, sbase + (c & 1) * BUF + 32768, wr, wc, lid, acc);
        __syncthreads();
        if (c + 2 <= 4)      { issueA(c + 2); issueB(c + 2); CPA_COMMIT(); }
        else if (c == 3)     { issueW2(); CPA_COMMIT(); }
    }

    // ---------- bias + LayerNorm + ReLU on fragments ----------
    float b1v[16], gv[16], bev[16];
#pragma unroll
    for (int nt = 0; nt < 8; nt++) {
        int col = wc * 64 + nt * 8 + 2 * (lid & 3);
        float2 t0 = *(const float2*)(B1 + col);
        float2 t1 = *(const float2*)(G + col);
        float2 t2 = *(const float2*)(BE + col);
        b1v[nt * 2] = t0.x; b1v[nt * 2 + 1] = t0.y;
        gv[nt * 2]  = t1.x; gv[nt * 2 + 1]  = t1.y;
        bev[nt * 2] = t2.x; bev[nt * 2 + 1] = t2.y;
    }
    float mus[4];
#pragma unroll
    for (int mt = 0; mt < 2; mt++)
#pragma unroll
        for (int rh = 0; rh < 2; rh++) {
            float s = 0.f;
#pragma unroll
            for (int nt = 0; nt < 8; nt++) {
                acc[mt][nt][rh * 2]     += b1v[nt * 2];
                acc[mt][nt][rh * 2 + 1] += b1v[nt * 2 + 1];
                s += acc[mt][nt][rh * 2] + acc[mt][nt][rh * 2 + 1];
            }
            s += __shfl_xor_sync(0xffffffffu, s, 1);
            s += __shfl_xor_sync(0xffffffffu, s, 2);
            if ((lid & 3) == 0)
                pS[(wr * 32 + mt * 16 + rh * 8 + (lid >> 2)) * 2 + wc] = s;
        }
    __syncthreads();
#pragma unroll
    for (int mt = 0; mt < 2; mt++)
#pragma unroll
        for (int rh = 0; rh < 2; rh++) {
            int rl = wr * 32 + mt * 16 + rh * 8 + (lid >> 2);
            float mu = (pS[rl * 2] + pS[rl * 2 + 1]) * 0.0078125f;
            mus[mt * 2 + rh] = mu;
            float q = 0.f;
#pragma unroll
            for (int nt = 0; nt < 8; nt++) {
                float d0 = acc[mt][nt][rh * 2] - mu;
                float d1 = acc[mt][nt][rh * 2 + 1] - mu;
                q += d0 * d0 + d1 * d1;
            }
            q += __shfl_xor_sync(0xffffffffu, q, 1);
            q += __shfl_xor_sync(0xffffffffu, q, 2);
            if ((lid & 3) == 0) pQ[rl * 2 + wc] = q;
        }
    __syncthreads();
    // normalize + relu + split to bf16 hi/lo into H tiles (buf0)
#pragma unroll
    for (int mt = 0; mt < 2; mt++)
#pragma unroll
        for (int rh = 0; rh < 2; rh++) {
            int rl = wr * 32 + mt * 16 + rh * 8 + (lid >> 2);
            float mu = mus[mt * 2 + rh];
            float rs = rsqrtf((pQ[rl * 2] + pQ[rl * 2 + 1]) * 0.0078125f + 1e-5f);
#pragma unroll
            for (int nt = 0; nt < 8; nt++) {
                float v0 = fmaxf((acc[mt][nt][rh * 2]     - mu) * rs * gv[nt * 2]     + bev[nt * 2], 0.f);
                float v1 = fmaxf((acc[mt][nt][rh * 2 + 1] - mu) * rs * gv[nt * 2 + 1] + bev[nt * 2 + 1], 0.f);
                float h0 = __bfloat162float(__float2bfloat16(v0));
                float h1 = __bfloat162float(__float2bfloat16(v1));
                uint32_t hiw = pack2(v0, v1);
                uint32_t low = pack2(v0 - h0, v1 - h1);
                uint32_t off = SW(rl * 128 + (nt * 8 + 2 * (lid & 3)) * 2);
                *(uint32_t*)(smc + wc * 32768 + off) = hiw;
                *(uint32_t*)(smc + wc * 32768 + 16384 + off) = low;
            }
        }
    CPA_WAIT(0);
    __syncthreads();

    // ---------- GEMM2 ----------
#pragma unroll
    for (int a = 0; a < 2; a++)
#pragma unroll
        for (int b = 0; b < 8; b++)
#pragma unroll
            for (int c = 0; c < 4; c++) acc[a][b][c] = 0.f;
#pragma unroll
    for (int ch = 0; ch < 2; ch++)
        mma_chunk(smc, sbase + ch * 32768, sbase + BUF + ch * 32768, wr, wc, lid, acc);

    // bias2
#pragma unroll
    for (int nt = 0; nt < 8; nt++) {
        float2 t = *(const float2*)(B2 + wc * 64 + nt * 8 + 2 * (lid & 3));
#pragma unroll
        for (int mt = 0; mt < 2; mt++) {
            acc[mt][nt][0] += t.x; acc[mt][nt][1] += t.y;
            acc[mt][nt][2] += t.x; acc[mt][nt][3] += t.y;
        }
    }

    // ---------- epilogues ----------
#pragma unroll
    for (int mt = 0; mt < 2; mt++)
#pragma unroll
        for (int rh = 0; rh < 2; rh++) {
            int rl = wr * 32 + mt * 16 + rh * 8 + (lid >> 2);
            int r  = row0 + rl;
            int d  = ds[rl];
            if constexpr (EPI == 1) {
#pragma unroll
                for (int hl = 0; hl < 4; hl++) {
                    const float* qp = g_q + (size_t)d * 128 + wc * 64 + hl * 16 + 2 * (lid & 3);
                    float2 q0 = *(const float2*)qp;
                    float2 q1 = *(const float2*)(qp + 8);
                    float part = acc[mt][2 * hl][rh * 2] * q0.x + acc[mt][2 * hl][rh * 2 + 1] * q0.y
                               + acc[mt][2 * hl + 1][rh * 2] * q1.x + acc[mt][2 * hl + 1][rh * 2 + 1] * q1.y;
                    part += __shfl_xor_sync(0xffffffffu, part, 1);
                    part += __shfl_xor_sync(0xffffffffu, part, 2);
                    if ((lid & 3) == 0) {
                        int hd = wc * 4 + hl;
                        float lg = part * 0.25f;
                        g_logits[(size_t)r * 8 + hd] = lg;
                        atomicMax(&g_mx[d * 8 + hd], fenc(lg));
                    }
                }
            } else {
                float eww = ew[r];
#pragma unroll
                for (int hl = 0; hl < 4; hl++) {
                    int hd = wc * 4 + hl;
                    float lg = g_logits[(size_t)r * 8 + hd];
                    float mx = fdec(g_mx[d * 8 + hd]);
                    float dn = g_den[d * 8 + hd];
                    float sc = __expf(lg - mx) / dn * eww;
                    float* op = g_aggr + (size_t)d * 128 + wc * 64 + hl * 16 + 2 * (lid & 3);
                    asm volatile("red.global.add.v2.f32 [%0], {%1,%2};" ::
                        "l"(op), "f"(acc[mt][2 * hl][rh * 2] * sc),
                                 "f"(acc[mt][2 * hl][rh * 2 + 1] * sc) : "memory");
                    asm volatile("red.global.add.v2.f32 [%0], {%1,%2};" ::
                        "l"(op + 8), "f"(acc[mt][2 * hl + 1][rh * 2] * sc),
                                     "f"(acc[mt][2 * hl + 1][rh * 2 + 1] * sc) : "memory");
                }
            }
        }
}

// ============================================================================
// SIMT fused MLP for the node MLPs (EPI 0: q, EPI 3: output)
// ============================================================================
#define HSTR 132

template <int DIN, int EPI>
__global__ void __launch_bounds__(256, 2)
fused_mlp(const float* __restrict__ hh,
          const float* __restrict__ W1, const float* __restrict__ B1,
          const float* __restrict__ G,  const float* __restrict__ BE,
          const float* __restrict__ W2, const float* __restrict__ B2,
          float* __restrict__ outp, int nrows)
{
    extern __shared__ float sm[];
    float* As = sm;
    float* Bs = sm + 16 * 128;
    float* Hs = sm + 32 * 128;

    const int tid   = threadIdx.x;
    const int tx    = tid & 15;
    const int ty    = tid >> 4;
    const int row0  = blockIdx.x * 128;
    const int myrow = ty * 8;
    const int mycol = tx * 8;
    const int rowL  = tid & 127;
    const int kL    = (tid >> 7) * 8;

    int rL = row0 + rowL;
    if (rL >= nrows) rL = nrows - 1;

    auto a_ptr = [&](int k0) -> const float* {
        int kk = k0 + kL;
        if constexpr (EPI == 0) {
            return hh + (size_t)rL * 128 + kk;
        } else {
            return (kk < 128) ? (g_aggr + (size_t)rL * 128 + kk)
                              : (hh + (size_t)rL * 128 + (kk - 128));
        }
    };

    float acc[8][8];
#pragma unroll
    for (int i = 0; i < 8; i++)
#pragma unroll
        for (int j = 0; j < 8; j++) acc[i][j] = 0.f;

    float4 pa0 = *(const float4*)(a_ptr(0));
    float4 pa1 = *(const float4*)(a_ptr(0) + 4);
    const float* wsrc = W1 + (size_t)ty * 128 + mycol;
    float4 pb0 = *(const float4*)(wsrc);
    float4 pb1 = *(const float4*)(wsrc + 4);

#pragma unroll 1
    for (int k0 = 0; k0 < DIN; k0 += 16) {
        As[(kL + 0) * 128 + rowL] = pa0.x;
        As[(kL + 1) * 128 + rowL] = pa0.y;
        As[(kL + 2) * 128 + rowL] = pa0.z;
        As[(kL + 3) * 128 + rowL] = pa0.w;
        As[(kL + 4) * 128 + rowL] = pa1.x;
        As[(kL + 5) * 128 + rowL] = pa1.y;
        As[(kL + 6) * 128 + rowL] = pa1.z;
        As[(kL + 7) * 128 + rowL] = pa1.w;
        *(float4*)(Bs + ty * 128 + mycol)     = pb0;
        *(float4*)(Bs + ty * 128 + mycol + 4) = pb1;
        __syncthreads();

        if (k0 + 16 < DIN) {
            pa0 = *(const float4*)(a_ptr(k0 + 16));
            pa1 = *(const float4*)(a_ptr(k0 + 16) + 4);
            const float* ws = W1 + (size_t)(k0 + 16 + ty) * 128 + mycol;
            pb0 = *(const float4*)(ws);
            pb1 = *(const float4*)(ws + 4);
        }
#pragma unroll
        for (int k = 0; k < 16; k++) {
            float4 a0 = *(float4*)(As + k * 128 + myrow);
            float4 a1 = *(float4*)(As + k * 128 + myrow + 4);
            float4 b0 = *(float4*)(Bs + k * 128 + mycol);
            float4 b1 = *(float4*)(Bs + k * 128 + mycol + 4);
            float a[8] = {a0.x, a0.y, a0.z, a0.w, a1.x, a1.y, a1.z, a1.w};
            float b[8] = {b0.x, b0.y, b0.z, b0.w, b1.x, b1.y, b1.z, b1.w};
#pragma unroll
            for (int i = 0; i < 8; i++)
#pragma unroll
                for (int j = 0; j < 8; j++)
                    acc[i][j] += a[i] * b[j];
        }
        __syncthreads();
    }

    {
        float gv[8], bev[8], b1v[8];
#pragma unroll
        for (int j = 0; j < 8; j++) {
            gv[j] = G[mycol + j]; bev[j] = BE[mycol + j]; b1v[j] = B1[mycol + j];
        }
#pragma unroll
        for (int i = 0; i < 8; i++) {
            float s = 0.f;
#pragma unroll
            for (int j = 0; j < 8; j++) { acc[i][j] += b1v[j]; s += acc[i][j]; }
            s += __shfl_xor_sync(0xffffffffu, s, 1);
            s += __shfl_xor_sync(0xffffffffu, s, 2);
            s += __shfl_xor_sync(0xffffffffu, s, 4);
            s += __shfl_xor_sync(0xffffffffu, s, 8);
            float mu = s * 0.0078125f;
            float s2 = 0.f;
#pragma unroll
            for (int j = 0; j < 8; j++) { float d = acc[i][j] - mu; s2 += d * d; }
            s2 += __shfl_xor_sync(0xffffffffu, s2, 1);
            s2 += __shfl_xor_sync(0xffffffffu, s2, 2);
            s2 += __shfl_xor_sync(0xffffffffu, s2, 4);
            s2 += __shfl_xor_sync(0xffffffffu, s2, 8);
            float rs = rsqrtf(s2 * 0.0078125f + 1e-5f);
#pragma unroll
            for (int j = 0; j < 8; j++)
                Hs[(myrow + i) * HSTR + mycol + j] =
                    fmaxf((acc[i][j] - mu) * rs * gv[j] + bev[j], 0.f);
        }
    }
    __syncthreads();

    float ac2[8][8];
#pragma unroll
    for (int i = 0; i < 8; i++)
#pragma unroll
        for (int j = 0; j < 8; j++) ac2[i][j] = 0.f;

    {
        const float* ws = W2 + (size_t)ty * 128 + mycol;
        pb0 = *(const float4*)(ws);
        pb1 = *(const float4*)(ws + 4);
    }
#pragma unroll 1
    for (int k0 = 0; k0 < 128; k0 += 16) {
        *(float4*)(Bs + ty * 128 + mycol)     = pb0;
        *(float4*)(Bs + ty * 128 + mycol + 4) = pb1;
        __syncthreads();
        if (k0 + 16 < 128) {
            const float* ws = W2 + (size_t)(k0 + 16 + ty) * 128 + mycol;
            pb0 = *(const float4*)(ws);
            pb1 = *(const float4*)(ws + 4);
        }
#pragma unroll
        for (int kb = 0; kb < 16; kb += 2) {
            float2 av[8];
#pragma unroll
            for (int i = 0; i < 8; i++)
                av[i] = *(float2*)(Hs + (myrow + i) * HSTR + k0 + kb);
#pragma unroll
            for (int kk = 0; kk < 2; kk++) {
                int k = kb + kk;
                float4 b0 = *(float4*)(Bs + k * 128 + mycol);
                float4 b1 = *(float4*)(Bs + k * 128 + mycol + 4);
                float b[8] = {b0.x, b0.y, b0.z, b0.w, b1.x, b1.y, b1.z, b1.w};
#pragma unroll
                for (int i = 0; i < 8; i++) {
                    float a = kk ? av[i].y : av[i].x;
#pragma unroll
                    for (int j = 0; j < 8; j++)
                        ac2[i][j] += a * b[j];
                }
            }
        }
        __syncthreads();
    }
#pragma unroll
    for (int j = 0; j < 8; j++) {
        float b2v = B2[mycol + j];
#pragma unroll
        for (int i = 0; i < 8; i++) ac2[i][j] += b2v;
    }

    float* dst0 = (EPI == 0) ? g_q : outp;
#pragma unroll
    for (int i = 0; i < 8; i++) {
        int r = row0 + myrow + i;
        if (r < nrows) {
            *(float4*)(dst0 + (size_t)r * 128 + mycol) =
                make_float4(ac2[i][0], ac2[i][1], ac2[i][2], ac2[i][3]);
            *(float4*)(dst0 + (size_t)r * 128 + mycol + 4) =
                make_float4(ac2[i][4], ac2[i][5], ac2[i][6], ac2[i][7]);
        }
    }
}

__global__ void den_kernel() {
    int i = blockIdx.x * blockDim.x + threadIdx.x;
    if (i >= EE * 8) return;
    int e = i >> 3, hd = i & 7;
    int d = g_dst[e];
    float lg = g_logits[i];
    float mx = fdec(g_mx[d * 8 + hd]);
    atomicAdd(&g_den[d * 8 + hd], __expf(lg - mx));
}

static const int NODE_SMEM = (32 * 128 + 128 * HSTR) * 4;

extern "C" void kernel_launch(void* const* d_in, const int* in_sizes, int n_in,
                              void* d_out, int out_size)
{
    const float* hPtr = (const float*)d_in[0];
    const float* ef   = (const float*)d_in[1];
    const float* ew   = (const float*)d_in[2];
    const void*  eidx = (const void*)d_in[3];
    const float* hk[6], *hv[6], *hq[6], *no[6];
    for (int i = 0; i < 6; i++) {
        hk[i] = (const float*)d_in[4 + i];
        hv[i] = (const float*)d_in[10 + i];
        hq[i] = (const float*)d_in[16 + i];
        no[i] = (const float*)d_in[22 + i];
    }
    float* outp = (float*)d_out;

    cudaFuncSetAttribute(fused_mlp<128, 0>, cudaFuncAttributeMaxDynamicSharedMemorySize, NODE_SMEM);
    cudaFuncSetAttribute(fused_mlp<256, 3>, cudaFuncAttributeMaxDynamicSharedMemorySize, NODE_SMEM);
    cudaFuncSetAttribute(edge_mlp<1, 0>, cudaFuncAttributeMaxDynamicSharedMemorySize, EDGE_SMEM);
    cudaFuncSetAttribute(edge_mlp<2, 1>, cudaFuncAttributeMaxDynamicSharedMemorySize, EDGE_SMEM);

    const int nodeBlocks = (NN + 127) / 128;
    const int edgeBlocks = EE / 128;                   // 6250
    const int flatBlocks = (NN * 128 + 255) / 256;
    const int denBlocks  = (EE * 8 + 255) / 256;
    const int idxBlocks  = (EE + 255) / 256;
    const int prepBlocks = (EE * 64 / 8 + NN * 128 / 8 + 255) / 256;

    detect_idx_kernel<<<1, 32>>>((const unsigned*)eidx);
    convert_idx_kernel<<<idxBlocks, 256>>>(eidx);
    prep_w<<<56, 256>>>(hk[0], hk[4], hv[0], hv[4]);
    prep_in<<<prepBlocks, 256>>>(ef, hPtr);
    init_kernel<<<flatBlocks, 256>>>();

    // q = MLP_hq(h)
    fused_mlp<128, 0><<<nodeBlocks, 256, NODE_SMEM>>>(
        hPtr, hq[0], hq[1], hq[2], hq[3], hq[4], hq[5], nullptr, NN);

    // k-MLP + logits + max (mma.sync)
    edge_mlp<1, 0><<<edgeBlocks, 256, EDGE_SMEM>>>(
        nullptr, hk[1], hk[2], hk[3], hk[5]);

    den_kernel<<<denBlocks, 256>>>();

    // v-MLP + alpha*e_w*v scatter (mma.sync)
    edge_mlp<2, 1><<<edgeBlocks, 256, EDGE_SMEM>>>(
        ew, hv[1], hv[2], hv[3], hv[5]);

    // out = MLP_no([aggr | h])
    fused_mlp<256, 3><<<nodeBlocks, 256, NODE_SMEM>>>(
        hPtr, no[0], no[1], no[2], no[3], no[4], no[5], outp, NN);
}

// round 7
// speedup vs baseline: 3.0122x; 1.1144x over previous
#include <cuda_runtime.h>
#include <cuda_bf16.h>
#include <cstdint>

#define NN 50000
#define EE 800000

// ---------------- scratch (device globals — allocation-free) ----------------
__device__ float    g_q[NN * 128];
__device__ float    g_logits[EE * 8];
__device__ float    g_den[NN * 8];
__device__ float    g_aggr[NN * 128];
__device__ int      g_src[EE];
__device__ int      g_dst[EE];
__device__ int      g_is64;
// pre-split, SW64-swizzled weight tiles: [mlp 0=hk,1=hv][tile 0..13][hi,lo] 8KB each
// tiles 0..9 = W1 32-k chunks, 10..13 = W2 32-k chunks. layout [n 0..127][k32], 64B rows.
__device__ char     g_wt[2 * 14 * 2 * 8192];
// pre-split inputs (bf16 hi / lo), row-major
__device__ uint4    g_efh[EE * 64 / 8];
__device__ uint4    g_efl[EE * 64 / 8];
__device__ uint4    g_hh[NN * 128 / 8];
__device__ uint4    g_hl[NN * 128 / 8];

// ======================= PTX helpers (base-target safe) =======================
__device__ __forceinline__ uint32_t smem_u32(const void* p) {
    uint32_t a;
    asm("{ .reg .u64 t; cvta.to.shared.u64 t, %1; cvt.u32.u64 %0, t; }" : "=r"(a) : "l"(p));
    return a;
}
__device__ __forceinline__ void cpa16(uint32_t dst, const void* src) {
    asm volatile("cp.async.cg.shared.global [%0], [%1], 16;" :: "r"(dst), "l"(src) : "memory");
}
#define CPA_COMMIT() asm volatile("cp.async.commit_group;" ::: "memory")
#define CPA_WAIT(n)  asm volatile("cp.async.wait_group %0;" :: "n"(n) : "memory")

__device__ __forceinline__ void ldsm4(uint32_t* r, uint32_t addr) {
    asm volatile("ldmatrix.sync.aligned.m8n8.x4.shared.b16 {%0,%1,%2,%3}, [%4];"
                 : "=r"(r[0]), "=r"(r[1]), "=r"(r[2]), "=r"(r[3]) : "r"(addr));
}
__device__ __forceinline__ void mma_bf16(float* c, const uint32_t* a, uint32_t b0, uint32_t b1) {
    asm volatile("mma.sync.aligned.m16n8k16.row.col.f32.bf16.bf16.f32 "
                 "{%0,%1,%2,%3}, {%4,%5,%6,%7}, {%8,%9}, {%0,%1,%2,%3};"
                 : "+f"(c[0]), "+f"(c[1]), "+f"(c[2]), "+f"(c[3])
                 : "r"(a[0]), "r"(a[1]), "r"(a[2]), "r"(a[3]), "r"(b0), "r"(b1));
}

#define SW64(o) ((o) ^ (((o) >> 3) & 0x30))

__device__ __forceinline__ unsigned pack2(float a, float b) {
    __nv_bfloat162 t = __floats2bfloat162_rn(a, b);
    return *reinterpret_cast<unsigned*>(&t);
}
__device__ __forceinline__ void split8(const float* x, uint4& hi, uint4& lo) {
    float h[8], l[8];
#pragma unroll
    for (int i = 0; i < 8; i++) {
        __nv_bfloat16 b = __float2bfloat16(x[i]);
        h[i] = __bfloat162float(b);
        l[i] = x[i] - h[i];
    }
    hi = make_uint4(pack2(h[0], h[1]), pack2(h[2], h[3]), pack2(h[4], h[5]), pack2(h[6], h[7]));
    lo = make_uint4(pack2(l[0], l[1]), pack2(l[2], l[3]), pack2(l[4], l[5]), pack2(l[6], l[7]));
}

// =================== setup kernels ===================
__global__ void detect_idx_kernel(const unsigned* __restrict__ raw) {
    if (threadIdx.x == 0 && blockIdx.x == 0) {
        int all_zero = 1;
        for (int i = 1; i < 128; i += 2)
            if (raw[i] != 0u) { all_zero = 0; break; }
        g_is64 = all_zero;
    }
}
__global__ void convert_idx_kernel(const void* __restrict__ raw) {
    int e = blockIdx.x * blockDim.x + threadIdx.x;
    if (e >= EE) return;
    if (g_is64) {
        const long long* p = (const long long*)raw;
        g_src[e] = (int)p[e];  g_dst[e] = (int)p[EE + e];
    } else {
        const int* p = (const int*)raw;
        g_src[e] = p[e];  g_dst[e] = p[EE + e];
    }
}
__global__ void init_kernel() {
    int i = blockIdx.x * blockDim.x + threadIdx.x;
    if (i < NN * 8) g_den[i] = 0.f;
    if (i < NN * 128) g_aggr[i] = 0.f;
}

// split ef + h into bf16 hi/lo (once, used by both edge kernels)
__global__ void prep_in(const float* __restrict__ ef, const float* __restrict__ hh) {
    const int totEf = EE * 64 / 8;
    const int totH  = NN * 128 / 8;
    int i = blockIdx.x * blockDim.x + threadIdx.x;
    if (i < totEf) {
        float x[8];
        float4 v0 = *(const float4*)(ef + (size_t)i * 8);
        float4 v1 = *(const float4*)(ef + (size_t)i * 8 + 4);
        x[0]=v0.x; x[1]=v0.y; x[2]=v0.z; x[3]=v0.w; x[4]=v1.x; x[5]=v1.y; x[6]=v1.z; x[7]=v1.w;
        uint4 hi, lo; split8(x, hi, lo);
        g_efh[i] = hi; g_efl[i] = lo;
    } else if (i < totEf + totH) {
        int j = i - totEf;
        float x[8];
        float4 v0 = *(const float4*)(hh + (size_t)j * 8);
        float4 v1 = *(const float4*)(hh + (size_t)j * 8 + 4);
        x[0]=v0.x; x[1]=v0.y; x[2]=v0.z; x[3]=v0.w; x[4]=v1.x; x[5]=v1.y; x[6]=v1.z; x[7]=v1.w;
        uint4 hi, lo; split8(x, hi, lo);
        g_hh[j] = hi; g_hl[j] = lo;
    }
}

// pre-split + pre-swizzle hk/hv weights into 32-k SW64 tiles (transposed [n][k])
__global__ void prep_w(const float* __restrict__ k1, const float* __restrict__ k2,
                       const float* __restrict__ v1, const float* __restrict__ v2) {
    int idx = blockIdx.x * blockDim.x + threadIdx.x;
    if (idx >= 2 * 14 * 512) return;
    int m = idx / 7168;
    int rem = idx % 7168;
    int t = rem >> 9;           // 0..13
    int r2 = rem & 511;
    int n = r2 >> 2, kg = r2 & 3;
    const float* W = (m == 0) ? (t < 10 ? k1 : k2) : (t < 10 ? v1 : v2);
    int k0 = (t < 10) ? t * 32 : (t - 10) * 32;
    float x[8];
#pragma unroll
    for (int j = 0; j < 8; j++)
        x[j] = W[(size_t)(k0 + kg * 8 + j) * 128 + n];
    uint4 hi, lo;
    split8(x, hi, lo);
    size_t slot = (size_t)(m * 14 + t) * 2;
    int off = SW64(n * 64 + kg * 16);
    *(uint4*)(g_wt + slot * 8192 + off) = hi;
    *(uint4*)(g_wt + (slot + 1) * 8192 + off) = lo;
}

// ============================================================================
// mma.sync edge MLP: CTA = 128 edges x 128 cols, 256 thr, warps 4(rows)x2(cols)
// 32-k chunks SW64, 2 CTAs/SM. H held in registers for GEMM2 (C-frag == A-frag).
// EPI 1: logits + den (no max). EPI 2: alpha*e_w*v scatter. MIDX: 0=hk, 1=hv.
// ============================================================================
#define OFF_EX  65536
#define OFF_PS  83968
#define OFF_PQ  84992
#define OFF_DS  86016
#define OFF_SS  86528
#define EDGE_SMEM 87040

__device__ __forceinline__ void mma_chunk32(uint32_t aHi, uint32_t bHi,
                                            int wrRow, int wcCol, int lid,
                                            float acc[2][8][4]) {
    const int mi  = lid >> 3;
    const int rin = ((mi & 1) << 3) + (lid & 7);
    const int kh  = (mi >> 1) << 4;
    const int nin = ((mi >> 1) << 3) + (lid & 7);
    const int khb = (mi & 1) << 4;
#pragma unroll
    for (int s = 0; s < 2; s++) {
        uint32_t ah[2][4], al[2][4];
#pragma unroll
        for (int mt = 0; mt < 2; mt++) {
            uint32_t off = SW64((wrRow + mt * 16 + rin) * 64 + s * 32 + kh);
            ldsm4(ah[mt], aHi + off);
            ldsm4(al[mt], aHi + 8192 + off);
        }
#pragma unroll
        for (int p = 0; p < 4; p++) {
            uint32_t boff = SW64((wcCol + p * 16 + nin) * 64 + s * 32 + khb);
            uint32_t bh4[4], bl4[4];
            ldsm4(bh4, bHi + boff);
            ldsm4(bl4, bHi + 8192 + boff);
#pragma unroll
            for (int mt = 0; mt < 2; mt++)
#pragma unroll
                for (int ntl = 0; ntl < 2; ntl++) {
                    float* C = acc[mt][p * 2 + ntl];
                    mma_bf16(C, ah[mt], bh4[ntl * 2], bh4[ntl * 2 + 1]);
                    mma_bf16(C, al[mt], bh4[ntl * 2], bh4[ntl * 2 + 1]);
                    mma_bf16(C, ah[mt], bl4[ntl * 2], bl4[ntl * 2 + 1]);
                }
        }
    }
}

template <int EPI, int MIDX>
__global__ void __launch_bounds__(256, 2)
edge_mlp(const float* __restrict__ ew,
         const float* __restrict__ B1, const float* __restrict__ G,
         const float* __restrict__ BE, const float* __restrict__ B2)
{
    extern __shared__ char smc[];
    const int tid = threadIdx.x;
    const int lid = tid & 31, wid = tid >> 5;
    const int wr = wid >> 1, wc = wid & 1;
    const int row0 = blockIdx.x * 128;
    uint32_t sbase = smem_u32(smc);
    int*   ds = (int*)(smc + OFF_DS);
    int*   ss = (int*)(smc + OFF_SS);
    float* pS = (float*)(smc + OFF_PS);
    float* pQ = (float*)(smc + OFF_PQ);

    if (tid < 128) { ds[tid] = g_dst[row0 + tid]; ss[tid] = g_src[row0 + tid]; }

    const int arow = tid >> 1, sel = tid & 1;

    auto issueA = [&](int c) {
        const char* src;
        if (c < 2)      src = (const char*)(sel ? g_efl : g_efh) + (size_t)(row0 + arow) * 128 + c * 64;
        else if (c < 6) src = (const char*)(sel ? g_hl : g_hh) + (size_t)ds[arow] * 256 + (c - 2) * 64;
        else            src = (const char*)(sel ? g_hl : g_hh) + (size_t)ss[arow] * 256 + (c - 6) * 64;
        uint32_t ab = sbase + (c & 1) * 32768 + sel * 8192;
#pragma unroll
        for (int g = 0; g < 4; g++)
            cpa16(ab + SW64(arow * 64 + g * 16), src + g * 16);
    };
    auto issueB = [&](int c) {
        const char* src = g_wt + (size_t)((MIDX * 14 + c) * 2) * 8192;
        uint32_t bb = sbase + (c & 1) * 32768 + 16384;
#pragma unroll
        for (int i = 0; i < 4; i++) {
            int ix = (tid + i * 256) * 16;
            cpa16(bb + ix, src + ix);
        }
    };
    auto issueW2 = [&](int half) {   // half 0: tiles 10,11 -> buf0; half 1: tiles 12,13 -> buf1
        const char* src = g_wt + (size_t)((MIDX * 14 + 10 + half * 2) * 2) * 8192;
        uint32_t db = sbase + half * 32768;
#pragma unroll
        for (int i = 0; i < 8; i++) {
            int ix = (tid + i * 256) * 16;
            cpa16(db + ix, src + ix);
        }
    };

    float acc[2][8][4];
#pragma unroll
    for (int a = 0; a < 2; a++)
#pragma unroll
        for (int b = 0; b < 8; b++)
#pragma unroll
            for (int c = 0; c < 4; c++) acc[a][b][c] = 0.f;

    issueA(0); issueB(0); CPA_COMMIT();
    __syncthreads();                       // ds/ss visible for later chunks
    issueA(1); issueB(1); CPA_COMMIT();

    // ---------------- GEMM1: 10 chunks of 32-k ----------------
#pragma unroll 1
    for (int c = 0; c < 10; c++) {
        CPA_WAIT(1);
        __syncthreads();
        mma_chunk32(sbase + (c & 1) * 32768, sbase + (c & 1) * 32768 + 16384,
                    wr * 32, wc * 64, lid, acc);
        __syncthreads();
        if (c + 2 < 10)  { issueA(c + 2); issueB(c + 2); CPA_COMMIT(); }
        else if (c == 8) { issueW2(0); CPA_COMMIT(); }
        else             { issueW2(1); CPA_COMMIT(); }
    }

    // ---------------- bias + LayerNorm (one pass) + ReLU + pack ----------------
    float b1v[16], gv[16], bev[16];
#pragma unroll
    for (int nt = 0; nt < 8; nt++) {
        int col = wc * 64 + nt * 8 + 2 * (lid & 3);
        float2 t0 = *(const float2*)(B1 + col);
        float2 t1 = *(const float2*)(G + col);
        float2 t2 = *(const float2*)(BE + col);
        b1v[nt * 2] = t0.x; b1v[nt * 2 + 1] = t0.y;
        gv[nt * 2]  = t1.x; gv[nt * 2 + 1]  = t1.y;
        bev[nt * 2] = t2.x; bev[nt * 2 + 1] = t2.y;
    }
#pragma unroll
    for (int mt = 0; mt < 2; mt++)
#pragma unroll
        for (int rh = 0; rh < 2; rh++) {
            float sv = 0.f, qv = 0.f;
#pragma unroll
            for (int nt = 0; nt < 8; nt++) {
                float x0 = acc[mt][nt][rh * 2]     + b1v[nt * 2];
                float x1 = acc[mt][nt][rh * 2 + 1] + b1v[nt * 2 + 1];
                acc[mt][nt][rh * 2] = x0; acc[mt][nt][rh * 2 + 1] = x1;
                sv += x0 + x1;
                qv += x0 * x0 + x1 * x1;
            }
            sv += __shfl_xor_sync(0xffffffffu, sv, 1);
            sv += __shfl_xor_sync(0xffffffffu, sv, 2);
            qv += __shfl_xor_sync(0xffffffffu, qv, 1);
            qv += __shfl_xor_sync(0xffffffffu, qv, 2);
            if ((lid & 3) == 0) {
                int rl = wr * 32 + mt * 16 + rh * 8 + (lid >> 2);
                pS[rl * 2 + wc] = sv;
                pQ[rl * 2 + wc] = qv;
            }
        }
    __syncthreads();

    uint32_t phi[2][8][2], plo[2][8][2];
#pragma unroll
    for (int mt = 0; mt < 2; mt++)
#pragma unroll
        for (int rh = 0; rh < 2; rh++) {
            int rl = wr * 32 + mt * 16 + rh * 8 + (lid >> 2);
            float mu = (pS[rl * 2] + pS[rl * 2 + 1]) * 0.0078125f;
            float var = (pQ[rl * 2] + pQ[rl * 2 + 1]) * 0.0078125f - mu * mu;
            float rs = rsqrtf(var + 1e-5f);
#pragma unroll
            for (int nt = 0; nt < 8; nt++) {
                float v0 = fmaxf((acc[mt][nt][rh * 2]     - mu) * rs * gv[nt * 2]     + bev[nt * 2], 0.f);
                float v1 = fmaxf((acc[mt][nt][rh * 2 + 1] - mu) * rs * gv[nt * 2 + 1] + bev[nt * 2 + 1], 0.f);
                float h0 = __bfloat162float(__float2bfloat16(v0));
                float h1 = __bfloat162float(__float2bfloat16(v1));
                phi[mt][nt][rh] = pack2(v0, v1);
                plo[mt][nt][rh] = pack2(v0 - h0, v1 - h1);
            }
        }

    CPA_WAIT(0);
    __syncthreads();   // W2 resident in buf0+buf1

    // ---------------- GEMM2 (H in regs) + epilogue, 4 n-quarters ----------------
    const int mi  = lid >> 3;
    const int nin = ((mi >> 1) << 3) + (lid & 7);
    const int khb = (mi & 1) << 4;

#pragma unroll 1
    for (int qn = 0; qn < 4; qn++) {
        float acc2[2][4][4];
#pragma unroll
        for (int a = 0; a < 2; a++)
#pragma unroll
            for (int b = 0; b < 4; b++)
#pragma unroll
                for (int c = 0; c < 4; c++) acc2[a][b][c] = 0.f;

#pragma unroll
        for (int s = 0; s < 4; s++) {
            uint32_t cb = sbase + (wc * 2 + (s >> 1)) * 16384;
            int sl = s & 1;
            uint32_t a_h[2][4], a_l[2][4];
#pragma unroll
            for (int mt = 0; mt < 2; mt++) {
                a_h[mt][0] = phi[mt][2 * s][0];     a_h[mt][1] = phi[mt][2 * s][1];
                a_h[mt][2] = phi[mt][2 * s + 1][0]; a_h[mt][3] = phi[mt][2 * s + 1][1];
                a_l[mt][0] = plo[mt][2 * s][0];     a_l[mt][1] = plo[mt][2 * s][1];
                a_l[mt][2] = plo[mt][2 * s + 1][0]; a_l[mt][3] = plo[mt][2 * s + 1][1];
            }
#pragma unroll
            for (int p = 0; p < 2; p++) {
                uint32_t boff = SW64((qn * 32 + p * 16 + nin) * 64 + sl * 32 + khb);
                uint32_t bh4[4], bl4[4];
                ldsm4(bh4, cb + boff);
                ldsm4(bl4, cb + 8192 + boff);
#pragma unroll
                for (int mt = 0; mt < 2; mt++)
#pragma unroll
                    for (int ntl = 0; ntl < 2; ntl++) {
                        float* C = acc2[mt][p * 2 + ntl];
                        mma_bf16(C, a_h[mt], bh4[ntl * 2], bh4[ntl * 2 + 1]);
                        mma_bf16(C, a_l[mt], bh4[ntl * 2], bh4[ntl * 2 + 1]);
                        mma_bf16(C, a_h[mt], bl4[ntl * 2], bl4[ntl * 2 + 1]);
                    }
            }
        }

        // exchange wc1 partial -> wc0, then epilogue by wc0
        __syncthreads();
        if (wc == 1) {
            float* ex = (float*)(smc + OFF_EX) + wr * (32 * 36);
#pragma unroll
            for (int mt = 0; mt < 2; mt++)
#pragma unroll
                for (int j = 0; j < 4; j++)
#pragma unroll
                    for (int rh = 0; rh < 2; rh++) {
                        int rr = mt * 16 + rh * 8 + (lid >> 2);
                        *(float2*)(ex + rr * 36 + j * 8 + 2 * (lid & 3)) =
                            make_float2(acc2[mt][j][rh * 2], acc2[mt][j][rh * 2 + 1]);
                    }
        }
        __syncthreads();
        if (wc == 0) {
            const float* ex = (const float*)(smc + OFF_EX) + wr * (32 * 36);
            float2 b2t[4];
#pragma unroll
            for (int j = 0; j < 4; j++)
                b2t[j] = *(const float2*)(B2 + qn * 32 + j * 8 + 2 * (lid & 3));
#pragma unroll
            for (int mt = 0; mt < 2; mt++)
#pragma unroll
                for (int rh = 0; rh < 2; rh++) {
                    int rr = mt * 16 + rh * 8 + (lid >> 2);
#pragma unroll
                    for (int j = 0; j < 4; j++) {
                        float2 t = *(const float2*)(ex + rr * 36 + j * 8 + 2 * (lid & 3));
                        acc2[mt][j][rh * 2]     += t.x + b2t[j].x;
                        acc2[mt][j][rh * 2 + 1] += t.y + b2t[j].y;
                    }
                }
#pragma unroll
            for (int mt = 0; mt < 2; mt++)
#pragma unroll
                for (int rh = 0; rh < 2; rh++) {
                    int rl = wr * 32 + mt * 16 + rh * 8 + (lid >> 2);
                    int r  = row0 + rl;
                    int d  = ds[rl];
                    if constexpr (EPI == 1) {
#pragma unroll
                        for (int hp = 0; hp < 2; hp++) {
                            int hd = qn * 2 + hp;
                            float part = 0.f;
#pragma unroll
                            for (int jj = 0; jj < 2; jj++) {
                                int j = hp * 2 + jj;
                                float2 q2 = *(const float2*)(g_q + (size_t)d * 128 + qn * 32 + j * 8 + 2 * (lid & 3));
                                part += acc2[mt][j][rh * 2] * q2.x + acc2[mt][j][rh * 2 + 1] * q2.y;
                            }
                            part += __shfl_xor_sync(0xffffffffu, part, 1);
                            part += __shfl_xor_sync(0xffffffffu, part, 2);
                            if ((lid & 3) == 0) {
                                float lg = part * 0.25f;
                                g_logits[(size_t)r * 8 + hd] = lg;
                                atomicAdd(&g_den[d * 8 + hd], __expf(lg));
                            }
                        }
                    } else {
                        float eww = ew[r];
#pragma unroll
                        for (int hp = 0; hp < 2; hp++) {
                            int hd = qn * 2 + hp;
                            float sc = __expf(g_logits[(size_t)r * 8 + hd]) / g_den[d * 8 + hd] * eww;
#pragma unroll
                            for (int jj = 0; jj < 2; jj++) {
                                int j = hp * 2 + jj;
                                float* op = g_aggr + (size_t)d * 128 + qn * 32 + j * 8 + 2 * (lid & 3);
                                asm volatile("red.global.add.v2.f32 [%0], {%1,%2};" ::
                                    "l"(op), "f"(acc2[mt][j][rh * 2] * sc),
                                             "f"(acc2[mt][j][rh * 2 + 1] * sc) : "memory");
                            }
                        }
                    }
                }
        }
    }
}

// ============================================================================
// SIMT fused MLP for the node MLPs (EPI 0: q, EPI 3: output)
// ============================================================================
#define HSTR 132

template <int DIN, int EPI>
__global__ void __launch_bounds__(256, 2)
fused_mlp(const float* __restrict__ hh,
          const float* __restrict__ W1, const float* __restrict__ B1,
          const float* __restrict__ G,  const float* __restrict__ BE,
          const float* __restrict__ W2, const float* __restrict__ B2,
          float* __restrict__ outp, int nrows)
{
    extern __shared__ float sm[];
    float* As = sm;
    float* Bs = sm + 16 * 128;
    float* Hs = sm + 32 * 128;

    const int tid   = threadIdx.x;
    const int tx    = tid & 15;
    const int ty    = tid >> 4;
    const int row0  = blockIdx.x * 128;
    const int myrow = ty * 8;
    const int mycol = tx * 8;
    const int rowL  = tid & 127;
    const int kL    = (tid >> 7) * 8;

    int rL = row0 + rowL;
    if (rL >= nrows) rL = nrows - 1;

    auto a_ptr = [&](int k0) -> const float* {
        int kk = k0 + kL;
        if constexpr (EPI == 0) {
            return hh + (size_t)rL * 128 + kk;
        } else {
            return (kk < 128) ? (g_aggr + (size_t)rL * 128 + kk)
                              : (hh + (size_t)rL * 128 + (kk - 128));
        }
    };

    float acc[8][8];
#pragma unroll
    for (int i = 0; i < 8; i++)
#pragma unroll
        for (int j = 0; j < 8; j++) acc[i][j] = 0.f;

    float4 pa0 = *(const float4*)(a_ptr(0));
    float4 pa1 = *(const float4*)(a_ptr(0) + 4);
    const float* wsrc = W1 + (size_t)ty * 128 + mycol;
    float4 pb0 = *(const float4*)(wsrc);
    float4 pb1 = *(const float4*)(wsrc + 4);

#pragma unroll 1
    for (int k0 = 0; k0 < DIN; k0 += 16) {
        As[(kL + 0) * 128 + rowL] = pa0.x;
        As[(kL + 1) * 128 + rowL] = pa0.y;
        As[(kL + 2) * 128 + rowL] = pa0.z;
        As[(kL + 3) * 128 + rowL] = pa0.w;
        As[(kL + 4) * 128 + rowL] = pa1.x;
        As[(kL + 5) * 128 + rowL] = pa1.y;
        As[(kL + 6) * 128 + rowL] = pa1.z;
        As[(kL + 7) * 128 + rowL] = pa1.w;
        *(float4*)(Bs + ty * 128 + mycol)     = pb0;
        *(float4*)(Bs + ty * 128 + mycol + 4) = pb1;
        __syncthreads();

        if (k0 + 16 < DIN) {
            pa0 = *(const float4*)(a_ptr(k0 + 16));
            pa1 = *(const float4*)(a_ptr(k0 + 16) + 4);
            const float* ws = W1 + (size_t)(k0 + 16 + ty) * 128 + mycol;
            pb0 = *(const float4*)(ws);
            pb1 = *(const float4*)(ws + 4);
        }
#pragma unroll
        for (int k = 0; k < 16; k++) {
            float4 a0 = *(float4*)(As + k * 128 + myrow);
            float4 a1 = *(float4*)(As + k * 128 + myrow + 4);
            float4 b0 = *(float4*)(Bs + k * 128 + mycol);
            float4 b1 = *(float4*)(Bs + k * 128 + mycol + 4);
            float a[8] = {a0.x, a0.y, a0.z, a0.w, a1.x, a1.y, a1.z, a1.w};
            float b[8] = {b0.x, b0.y, b0.z, b0.w, b1.x, b1.y, b1.z, b1.w};
#pragma unroll
            for (int i = 0; i < 8; i++)
#pragma unroll
                for (int j = 0; j < 8; j++)
                    acc[i][j] += a[i] * b[j];
        }
        __syncthreads();
    }

    {
        float gv[8], bev[8], b1v[8];
#pragma unroll
        for (int j = 0; j < 8; j++) {
            gv[j] = G[mycol + j]; bev[j] = BE[mycol + j]; b1v[j] = B1[mycol + j];
        }
#pragma unroll
        for (int i = 0; i < 8; i++) {
            float s = 0.f;
#pragma unroll
            for (int j = 0; j < 8; j++) { acc[i][j] += b1v[j]; s += acc[i][j]; }
            s += __shfl_xor_sync(0xffffffffu, s, 1);
            s += __shfl_xor_sync(0xffffffffu, s, 2);
            s += __shfl_xor_sync(0xffffffffu, s, 4);
            s += __shfl_xor_sync(0xffffffffu, s, 8);
            float mu = s * 0.0078125f;
            float s2 = 0.f;
#pragma unroll
            for (int j = 0; j < 8; j++) { float d = acc[i][j] - mu; s2 += d * d; }
            s2 += __shfl_xor_sync(0xffffffffu, s2, 1);
            s2 += __shfl_xor_sync(0xffffffffu, s2, 2);
            s2 += __shfl_xor_sync(0xffffffffu, s2, 4);
            s2 += __shfl_xor_sync(0xffffffffu, s2, 8);
            float rs = rsqrtf(s2 * 0.0078125f + 1e-5f);
#pragma unroll
            for (int j = 0; j < 8; j++)
                Hs[(myrow + i) * HSTR + mycol + j] =
                    fmaxf((acc[i][j] - mu) * rs * gv[j] + bev[j], 0.f);
        }
    }
    __syncthreads();

    float ac2[8][8];
#pragma unroll
    for (int i = 0; i < 8; i++)
#pragma unroll
        for (int j = 0; j < 8; j++) ac2[i][j] = 0.f;

    {
        const float* ws = W2 + (size_t)ty * 128 + mycol;
        pb0 = *(const float4*)(ws);
        pb1 = *(const float4*)(ws + 4);
    }
#pragma unroll 1
    for (int k0 = 0; k0 < 128; k0 += 16) {
        *(float4*)(Bs + ty * 128 + mycol)     = pb0;
        *(float4*)(Bs + ty * 128 + mycol + 4) = pb1;
        __syncthreads();
        if (k0 + 16 < 128) {
            const float* ws = W2 + (size_t)(k0 + 16 + ty) * 128 + mycol;
            pb0 = *(const float4*)(ws);
            pb1 = *(const float4*)(ws + 4);
        }
#pragma unroll
        for (int kb = 0; kb < 16; kb += 2) {
            float2 av[8];
#pragma unroll
            for (int i = 0; i < 8; i++)
                av[i] = *(float2*)(Hs + (myrow + i) * HSTR + k0 + kb);
#pragma unroll
            for (int kk = 0; kk < 2; kk++) {
                int k = kb + kk;
                float4 b0 = *(float4*)(Bs + k * 128 + mycol);
                float4 b1 = *(float4*)(Bs + k * 128 + mycol + 4);
                float b[8] = {b0.x, b0.y, b0.z, b0.w, b1.x, b1.y, b1.z, b1.w};
#pragma unroll
                for (int i = 0; i < 8; i++) {
                    float a = kk ? av[i].y : av[i].x;
#pragma unroll
                    for (int j = 0; j < 8; j++)
                        ac2[i][j] += a * b[j];
                }
            }
        }
        __syncthreads();
    }
#pragma unroll
    for (int j = 0; j < 8; j++) {
        float b2v = B2[mycol + j];
#pragma unroll
        for (int i = 0; i < 8; i++) ac2[i][j] += b2v;
    }

    float* dst0 = (EPI == 0) ? g_q : outp;
#pragma unroll
    for (int i = 0; i < 8; i++) {
        int r = row0 + myrow + i;
        if (r < nrows) {
            *(float4*)(dst0 + (size_t)r * 128 + mycol) =
                make_float4(ac2[i][0], ac2[i][1], ac2[i][2], ac2[i][3]);
            *(float4*)(dst0 + (size_t)r * 128 + mycol + 4) =
                make_float4(ac2[i][4], ac2[i][5], ac2[i][6], ac2[i][7]);
        }
    }
}

static const int NODE_SMEM = (32 * 128 + 128 * HSTR) * 4;

extern "C" void kernel_launch(void* const* d_in, const int* in_sizes, int n_in,
                              void* d_out, int out_size)
{
    const float* hPtr = (const float*)d_in[0];
    const float* ef   = (const float*)d_in[1];
    const float* ew   = (const float*)d_in[2];
    const void*  eidx = (const void*)d_in[3];
    const float* hk[6], *hv[6], *hq[6], *no[6];
    for (int i = 0; i < 6; i++) {
        hk[i] = (const float*)d_in[4 + i];
        hv[i] = (const float*)d_in[10 + i];
        hq[i] = (const float*)d_in[16 + i];
        no[i] = (const float*)d_in[22 + i];
    }
    float* outp = (float*)d_out;

    cudaFuncSetAttribute(fused_mlp<128, 0>, cudaFuncAttributeMaxDynamicSharedMemorySize, NODE_SMEM);
    cudaFuncSetAttribute(fused_mlp<256, 3>, cudaFuncAttributeMaxDynamicSharedMemorySize, NODE_SMEM);
    cudaFuncSetAttribute(edge_mlp<1, 0>, cudaFuncAttributeMaxDynamicSharedMemorySize, EDGE_SMEM);
    cudaFuncSetAttribute(edge_mlp<2, 1>, cudaFuncAttributeMaxDynamicSharedMemorySize, EDGE_SMEM);

    const int nodeBlocks = (NN + 127) / 128;
    const int edgeBlocks = EE / 128;                   // 6250
    const int flatBlocks = (NN * 128 + 255) / 256;
    const int idxBlocks  = (EE + 255) / 256;
    const int prepBlocks = (EE * 64 / 8 + NN * 128 / 8 + 255) / 256;

    detect_idx_kernel<<<1, 32>>>((const unsigned*)eidx);
    convert_idx_kernel<<<idxBlocks, 256>>>(eidx);
    prep_w<<<56, 256>>>(hk[0], hk[4], hv[0], hv[4]);
    prep_in<<<prepBlocks, 256>>>(ef, hPtr);
    init_kernel<<<flatBlocks, 256>>>();

    // q = MLP_hq(h)
    fused_mlp<128, 0><<<nodeBlocks, 256, NODE_SMEM>>>(
        hPtr, hq[0], hq[1], hq[2], hq[3], hq[4], hq[5], nullptr, NN);

    // k-MLP + logits + den (mma.sync, no max)
    edge_mlp<1, 0><<<edgeBlocks, 256, EDGE_SMEM>>>(
        nullptr, hk[1], hk[2], hk[3], hk[5]);

    // v-MLP + alpha*e_w*v scatter (mma.sync)
    edge_mlp<2, 1><<<edgeBlocks, 256, EDGE_SMEM>>>(
        ew, hv[1], hv[2], hv[3], hv[5]);

    // out = MLP_no([aggr | h])
    fused_mlp<256, 3><<<nodeBlocks, 256, NODE_SMEM>>>(
        hPtr, no[0], no[1], no[2], no[3], no[4], no[5], outp, NN);
}

// round 8
// speedup vs baseline: 5.2896x; 1.7560x over previous
#include <cuda_runtime.h>
#include <cuda_fp16.h>
#include <cstdint>

#define NN 50000
#define EE 800000

// ---------------- scratch (device globals — allocation-free) ----------------
__device__ float    g_q[NN * 128];
__device__ float    g_logits[EE * 8];
__device__ float    g_den[NN * 8];
__device__ float    g_aggr[NN * 128];
__device__ int      g_src[EE];
__device__ int      g_dst[EE];
__device__ int      g_is64;
// fp16, SW64-swizzled weight tiles: [mlp 0=hk,1=hv][tile 0..13] 8KB each
// tiles 0..9 = W1 32-k chunks, 10..13 = W2 32-k chunks. layout [n 0..127][k32], 64B rows.
__device__ char     g_wt[2 * 14 * 8192];
// fp16 inputs, row-major
__device__ __align__(16) __half g_ef[(size_t)EE * 64];
__device__ __align__(16) __half g_h[(size_t)NN * 128];

// ======================= PTX helpers (base-target safe) =======================
__device__ __forceinline__ uint32_t smem_u32(const void* p) {
    uint32_t a;
    asm("{ .reg .u64 t; cvta.to.shared.u64 t, %1; cvt.u32.u64 %0, t; }" : "=r"(a) : "l"(p));
    return a;
}
__device__ __forceinline__ void cpa16(uint32_t dst, const void* src) {
    asm volatile("cp.async.cg.shared.global [%0], [%1], 16;" :: "r"(dst), "l"(src) : "memory");
}
#define CPA_COMMIT() asm volatile("cp.async.commit_group;" ::: "memory")
#define CPA_WAIT(n)  asm volatile("cp.async.wait_group %0;" :: "n"(n) : "memory")

__device__ __forceinline__ void ldsm4(uint32_t* r, uint32_t addr) {
    asm volatile("ldmatrix.sync.aligned.m8n8.x4.shared.b16 {%0,%1,%2,%3}, [%4];"
                 : "=r"(r[0]), "=r"(r[1]), "=r"(r[2]), "=r"(r[3]) : "r"(addr));
}
__device__ __forceinline__ void mma_f16(float* c, const uint32_t* a, uint32_t b0, uint32_t b1) {
    asm volatile("mma.sync.aligned.m16n8k16.row.col.f32.f16.f16.f32 "
                 "{%0,%1,%2,%3}, {%4,%5,%6,%7}, {%8,%9}, {%0,%1,%2,%3};"
                 : "+f"(c[0]), "+f"(c[1]), "+f"(c[2]), "+f"(c[3])
                 : "r"(a[0]), "r"(a[1]), "r"(a[2]), "r"(a[3]), "r"(b0), "r"(b1));
}

#define SW64(o) ((o) ^ (((o) >> 3) & 0x30))

__device__ __forceinline__ unsigned packh2(float a, float b) {
    __half2 t = __floats2half2_rn(a, b);
    return *reinterpret_cast<unsigned*>(&t);
}
__device__ __forceinline__ uint4 packh8(const float* x) {
    return make_uint4(packh2(x[0], x[1]), packh2(x[2], x[3]),
                      packh2(x[4], x[5]), packh2(x[6], x[7]));
}

// =================== setup kernels ===================
__global__ void detect_idx_kernel(const unsigned* __restrict__ raw) {
    if (threadIdx.x == 0 && blockIdx.x == 0) {
        int all_zero = 1;
        for (int i = 1; i < 128; i += 2)
            if (raw[i] != 0u) { all_zero = 0; break; }
        g_is64 = all_zero;
    }
}
__global__ void convert_idx_kernel(const void* __restrict__ raw) {
    int e = blockIdx.x * blockDim.x + threadIdx.x;
    if (e >= EE) return;
    if (g_is64) {
        const long long* p = (const long long*)raw;
        g_src[e] = (int)p[e];  g_dst[e] = (int)p[EE + e];
    } else {
        const int* p = (const int*)raw;
        g_src[e] = p[e];  g_dst[e] = p[EE + e];
    }
}
__global__ void init_kernel() {
    int i = blockIdx.x * blockDim.x + threadIdx.x;
    if (i < NN * 8) g_den[i] = 0.f;
    if (i < NN * 128) g_aggr[i] = 0.f;
}

// convert ef + h to fp16 (once, used by both edge kernels)
__global__ void prep_in(const float* __restrict__ ef, const float* __restrict__ hh) {
    const int totEf = EE * 64 / 8;
    const int totH  = NN * 128 / 8;
    int i = blockIdx.x * blockDim.x + threadIdx.x;
    if (i < totEf) {
        float x[8];
        float4 v0 = *(const float4*)(ef + (size_t)i * 8);
        float4 v1 = *(const float4*)(ef + (size_t)i * 8 + 4);
        x[0]=v0.x; x[1]=v0.y; x[2]=v0.z; x[3]=v0.w; x[4]=v1.x; x[5]=v1.y; x[6]=v1.z; x[7]=v1.w;
        *(uint4*)(g_ef + (size_t)i * 8) = packh8(x);
    } else if (i < totEf + totH) {
        int j = i - totEf;
        float x[8];
        float4 v0 = *(const float4*)(hh + (size_t)j * 8);
        float4 v1 = *(const float4*)(hh + (size_t)j * 8 + 4);
        x[0]=v0.x; x[1]=v0.y; x[2]=v0.z; x[3]=v0.w; x[4]=v1.x; x[5]=v1.y; x[6]=v1.z; x[7]=v1.w;
        *(uint4*)(g_h + (size_t)j * 8) = packh8(x);
    }
}

// fp16 + pre-swizzle hk/hv weights into 32-k SW64 tiles (transposed [n][k])
__global__ void prep_w(const float* __restrict__ k1, const float* __restrict__ k2,
                       const float* __restrict__ v1, const float* __restrict__ v2) {
    int idx = blockIdx.x * blockDim.x + threadIdx.x;
    if (idx >= 2 * 14 * 512) return;
    int m = idx / 7168;
    int rem = idx % 7168;
    int t = rem >> 9;           // 0..13
    int r2 = rem & 511;
    int n = r2 >> 2, kg = r2 & 3;
    const float* W = (m == 0) ? (t < 10 ? k1 : k2) : (t < 10 ? v1 : v2);
    int k0 = (t < 10) ? t * 32 : (t - 10) * 32;
    float x[8];
#pragma unroll
    for (int j = 0; j < 8; j++)
        x[j] = W[(size_t)(k0 + kg * 8 + j) * 128 + n];
    int off = SW64(n * 64 + kg * 16);
    *(uint4*)(g_wt + (size_t)(m * 14 + t) * 8192 + off) = packh8(x);
}

// ============================================================================
// fp16 mma.sync edge MLP: CTA = 128 edges x 128 cols, 256 thr, warps 4x2.
// 32-k chunks SW64 (A 8KB + B 8KB per buffer), H in registers for GEMM2.
// EPI 1: logits + den. EPI 2: alpha*e_w*v scatter. MIDX: 0=hk, 1=hv.
// ============================================================================
#define OFF_W2  32768
#define OFF_EX  65536
#define OFF_PS  83968
#define OFF_PQ  84992
#define OFF_DS  86016
#define OFF_SS  86528
#define EDGE_SMEM 87040

__device__ __forceinline__ void mma_chunk32(uint32_t aB, uint32_t bB,
                                            int wrRow, int wcCol, int lid,
                                            float acc[2][8][4]) {
    const int mi  = lid >> 3;
    const int rin = ((mi & 1) << 3) + (lid & 7);
    const int kh  = (mi >> 1) << 4;
    const int nin = ((mi >> 1) << 3) + (lid & 7);
    const int khb = (mi & 1) << 4;
#pragma unroll
    for (int s = 0; s < 2; s++) {
        uint32_t ah[2][4];
#pragma unroll
        for (int mt = 0; mt < 2; mt++)
            ldsm4(ah[mt], aB + SW64((wrRow + mt * 16 + rin) * 64 + s * 32 + kh));
#pragma unroll
        for (int p = 0; p < 4; p++) {
            uint32_t bh4[4];
            ldsm4(bh4, bB + SW64((wcCol + p * 16 + nin) * 64 + s * 32 + khb));
#pragma unroll
            for (int mt = 0; mt < 2; mt++)
#pragma unroll
                for (int ntl = 0; ntl < 2; ntl++)
                    mma_f16(acc[mt][p * 2 + ntl], ah[mt], bh4[ntl * 2], bh4[ntl * 2 + 1]);
        }
    }
}

template <int EPI, int MIDX>
__global__ void __launch_bounds__(256, 2)
edge_mlp(const float* __restrict__ ew,
         const float* __restrict__ B1, const float* __restrict__ G,
         const float* __restrict__ BE, const float* __restrict__ B2)
{
    extern __shared__ char smc[];
    const int tid = threadIdx.x;
    const int lid = tid & 31, wid = tid >> 5;
    const int wr = wid >> 1, wc = wid & 1;
    const int row0 = blockIdx.x * 128;
    uint32_t sbase = smem_u32(smc);
    int*   ds = (int*)(smc + OFF_DS);
    int*   ss = (int*)(smc + OFF_SS);
    float* pS = (float*)(smc + OFF_PS);
    float* pQ = (float*)(smc + OFF_PQ);

    if (tid < 128) { ds[tid] = g_dst[row0 + tid]; ss[tid] = g_src[row0 + tid]; }

    const int arow = tid >> 1, sel = tid & 1;

    auto issueA = [&](int c) {
        const char* src;
        if (c < 2)      src = (const char*)g_ef + (size_t)(row0 + arow) * 128 + c * 64;
        else if (c < 6) src = (const char*)g_h + (size_t)ds[arow] * 256 + (c - 2) * 64;
        else            src = (const char*)g_h + (size_t)ss[arow] * 256 + (c - 6) * 64;
        uint32_t ab = sbase + (c & 1) * 16384;
#pragma unroll
        for (int g = 0; g < 2; g++)
            cpa16(ab + SW64(arow * 64 + sel * 32 + g * 16), src + sel * 32 + g * 16);
    };
    auto issueB = [&](int c) {
        const char* src = g_wt + (size_t)((MIDX * 14 + c)) * 8192;
        uint32_t bb = sbase + (c & 1) * 16384 + 8192;
#pragma unroll
        for (int i = 0; i < 2; i++) {
            int ix = (tid + i * 256) * 16;
            cpa16(bb + ix, src + ix);
        }
    };
    auto issueW2 = [&]() {
#pragma unroll
        for (int t = 0; t < 4; t++) {
            const char* src = g_wt + (size_t)((MIDX * 14 + 10 + t)) * 8192;
            uint32_t db = sbase + OFF_W2 + t * 8192;
#pragma unroll
            for (int i = 0; i < 2; i++) {
                int ix = (tid + i * 256) * 16;
                cpa16(db + ix, src + ix);
            }
        }
    };

    float acc[2][8][4];
#pragma unroll
    for (int a = 0; a < 2; a++)
#pragma unroll
        for (int b = 0; b < 8; b++)
#pragma unroll
            for (int c = 0; c < 4; c++) acc[a][b][c] = 0.f;

    issueA(0); issueB(0); CPA_COMMIT();
    __syncthreads();                       // ds/ss visible for later chunks
    issueA(1); issueB(1); CPA_COMMIT();

    // ---------------- GEMM1: 10 chunks of 32-k ----------------
#pragma unroll 1
    for (int c = 0; c < 10; c++) {
        CPA_WAIT(1);
        __syncthreads();
        mma_chunk32(sbase + (c & 1) * 16384, sbase + (c & 1) * 16384 + 8192,
                    wr * 32, wc * 64, lid, acc);
        __syncthreads();
        if (c + 2 < 10)  { issueA(c + 2); issueB(c + 2); CPA_COMMIT(); }
        else if (c == 8) { issueW2(); CPA_COMMIT(); }
    }

    // ---------------- bias + LayerNorm (one pass) + ReLU + pack ----------------
    float b1v[16], gv[16], bev[16];
#pragma unroll
    for (int nt = 0; nt < 8; nt++) {
        int col = wc * 64 + nt * 8 + 2 * (lid & 3);
        float2 t0 = *(const float2*)(B1 + col);
        float2 t1 = *(const float2*)(G + col);
        float2 t2 = *(const float2*)(BE + col);
        b1v[nt * 2] = t0.x; b1v[nt * 2 + 1] = t0.y;
        gv[nt * 2]  = t1.x; gv[nt * 2 + 1]  = t1.y;
        bev[nt * 2] = t2.x; bev[nt * 2 + 1] = t2.y;
    }
#pragma unroll
    for (int mt = 0; mt < 2; mt++)
#pragma unroll
        for (int rh = 0; rh < 2; rh++) {
            float sv = 0.f, qv = 0.f;
#pragma unroll
            for (int nt = 0; nt < 8; nt++) {
                float x0 = acc[mt][nt][rh * 2]     + b1v[nt * 2];
                float x1 = acc[mt][nt][rh * 2 + 1] + b1v[nt * 2 + 1];
                acc[mt][nt][rh * 2] = x0; acc[mt][nt][rh * 2 + 1] = x1;
                sv += x0 + x1;
                qv += x0 * x0 + x1 * x1;
            }
            sv += __shfl_xor_sync(0xffffffffu, sv, 1);
            sv += __shfl_xor_sync(0xffffffffu, sv, 2);
            qv += __shfl_xor_sync(0xffffffffu, qv, 1);
            qv += __shfl_xor_sync(0xffffffffu, qv, 2);
            if ((lid & 3) == 0) {
                int rl = wr * 32 + mt * 16 + rh * 8 + (lid >> 2);
                pS[rl * 2 + wc] = sv;
                pQ[rl * 2 + wc] = qv;
            }
        }
    __syncthreads();

    uint32_t phi[2][8][2];
#pragma unroll
    for (int mt = 0; mt < 2; mt++)
#pragma unroll
        for (int rh = 0; rh < 2; rh++) {
            int rl = wr * 32 + mt * 16 + rh * 8 + (lid >> 2);
            float mu = (pS[rl * 2] + pS[rl * 2 + 1]) * 0.0078125f;
            float var = (pQ[rl * 2] + pQ[rl * 2 + 1]) * 0.0078125f - mu * mu;
            float rs = rsqrtf(var + 1e-5f);
#pragma unroll
            for (int nt = 0; nt < 8; nt++) {
                float v0 = fmaxf((acc[mt][nt][rh * 2]     - mu) * rs * gv[nt * 2]     + bev[nt * 2], 0.f);
                float v1 = fmaxf((acc[mt][nt][rh * 2 + 1] - mu) * rs * gv[nt * 2 + 1] + bev[nt * 2 + 1], 0.f);
                phi[mt][nt][rh] = packh2(v0, v1);
            }
        }

    CPA_WAIT(0);
    __syncthreads();   // W2 resident

    // ---------------- GEMM2 (H in regs) + epilogue, 4 n-quarters ----------------
    const int mi  = lid >> 3;
    const int nin = ((mi >> 1) << 3) + (lid & 7);
    const int khb = (mi & 1) << 4;

#pragma unroll 1
    for (int qn = 0; qn < 4; qn++) {
        float acc2[2][4][4];
#pragma unroll
        for (int a = 0; a < 2; a++)
#pragma unroll
            for (int b = 0; b < 4; b++)
#pragma unroll
                for (int c = 0; c < 4; c++) acc2[a][b][c] = 0.f;

#pragma unroll
        for (int s = 0; s < 4; s++) {
            uint32_t cb = sbase + OFF_W2 + (wc * 2 + (s >> 1)) * 8192;
            int sl = s & 1;
            uint32_t a_h[2][4];
#pragma unroll
            for (int mt = 0; mt < 2; mt++) {
                a_h[mt][0] = phi[mt][2 * s][0];     a_h[mt][1] = phi[mt][2 * s][1];
                a_h[mt][2] = phi[mt][2 * s + 1][0]; a_h[mt][3] = phi[mt][2 * s + 1][1];
            }
#pragma unroll
            for (int p = 0; p < 2; p++) {
                uint32_t bh4[4];
                ldsm4(bh4, cb + SW64((qn * 32 + p * 16 + nin) * 64 + sl * 32 + khb));
#pragma unroll
                for (int mt = 0; mt < 2; mt++)
#pragma unroll
                    for (int ntl = 0; ntl < 2; ntl++)
                        mma_f16(acc2[mt][p * 2 + ntl], a_h[mt], bh4[ntl * 2], bh4[ntl * 2 + 1]);
            }
        }

        // exchange wc1 partial -> wc0, then epilogue by wc0
        __syncthreads();
        if (wc == 1) {
            float* ex = (float*)(smc + OFF_EX) + wr * (32 * 36);
#pragma unroll
            for (int mt = 0; mt < 2; mt++)
#pragma unroll
                for (int j = 0; j < 4; j++)
#pragma unroll
                    for (int rh = 0; rh < 2; rh++) {
                        int rr = mt * 16 + rh * 8 + (lid >> 2);
                        *(float2*)(ex + rr * 36 + j * 8 + 2 * (lid & 3)) =
                            make_float2(acc2[mt][j][rh * 2], acc2[mt][j][rh * 2 + 1]);
                    }
        }
        __syncthreads();
        if (wc == 0) {
            const float* ex = (const float*)(smc + OFF_EX) + wr * (32 * 36);
            float2 b2t[4];
#pragma unroll
            for (int j = 0; j < 4; j++)
                b2t[j] = *(const float2*)(B2 + qn * 32 + j * 8 + 2 * (lid & 3));
#pragma unroll
            for (int mt = 0; mt < 2; mt++)
#pragma unroll
                for (int rh = 0; rh < 2; rh++) {
                    int rr = mt * 16 + rh * 8 + (lid >> 2);
#pragma unroll
                    for (int j = 0; j < 4; j++) {
                        float2 t = *(const float2*)(ex + rr * 36 + j * 8 + 2 * (lid & 3));
                        acc2[mt][j][rh * 2]     += t.x + b2t[j].x;
                        acc2[mt][j][rh * 2 + 1] += t.y + b2t[j].y;
                    }
                }
#pragma unroll
            for (int mt = 0; mt < 2; mt++)
#pragma unroll
                for (int rh = 0; rh < 2; rh++) {
                    int rl = wr * 32 + mt * 16 + rh * 8 + (lid >> 2);
                    int r  = row0 + rl;
                    int d  = ds[rl];
                    if constexpr (EPI == 1) {
#pragma unroll
                        for (int hp = 0; hp < 2; hp++) {
                            int hd = qn * 2 + hp;
                            float part = 0.f;
#pragma unroll
                            for (int jj = 0; jj < 2; jj++) {
                                int j = hp * 2 + jj;
                                float2 q2 = *(const float2*)(g_q + (size_t)d * 128 + qn * 32 + j * 8 + 2 * (lid & 3));
                                part += acc2[mt][j][rh * 2] * q2.x + acc2[mt][j][rh * 2 + 1] * q2.y;
                            }
                            part += __shfl_xor_sync(0xffffffffu, part, 1);
                            part += __shfl_xor_sync(0xffffffffu, part, 2);
                            if ((lid & 3) == 0) {
                                float lg = part * 0.25f;
                                g_logits[(size_t)r * 8 + hd] = lg;
                                atomicAdd(&g_den[d * 8 + hd], __expf(lg));
                            }
                        }
                    } else {
                        float eww = ew[r];
#pragma unroll
                        for (int hp = 0; hp < 2; hp++) {
                            int hd = qn * 2 + hp;
                            float sc = __expf(g_logits[(size_t)r * 8 + hd]) / g_den[d * 8 + hd] * eww;
#pragma unroll
                            for (int jj = 0; jj < 2; jj++) {
                                int j = hp * 2 + jj;
                                float* op = g_aggr + (size_t)d * 128 + qn * 32 + j * 8 + 2 * (lid & 3);
                                asm volatile("red.global.add.v2.f32 [%0], {%1,%2};" ::
                                    "l"(op), "f"(acc2[mt][j][rh * 2] * sc),
                                             "f"(acc2[mt][j][rh * 2 + 1] * sc) : "memory");
                            }
                        }
                    }
                }
        }
    }
}

// ============================================================================
// SIMT fused MLP for the node MLPs (EPI 0: q, EPI 3: output)
// ============================================================================
#define HSTR 132

template <int DIN, int EPI>
__global__ void __launch_bounds__(256, 2)
fused_mlp(const float* __restrict__ hh,
          const float* __restrict__ W1, const float* __restrict__ B1,
          const float* __restrict__ G,  const float* __restrict__ BE,
          const float* __restrict__ W2, const float* __restrict__ B2,
          float* __restrict__ outp, int nrows)
{
    extern __shared__ float sm[];
    float* As = sm;
    float* Bs = sm + 16 * 128;
    float* Hs = sm + 32 * 128;

    const int tid   = threadIdx.x;
    const int tx    = tid & 15;
    const int ty    = tid >> 4;
    const int row0  = blockIdx.x * 128;
    const int myrow = ty * 8;
    const int mycol = tx * 8;
    const int rowL  = tid & 127;
    const int kL    = (tid >> 7) * 8;

    int rL = row0 + rowL;
    if (rL >= nrows) rL = nrows - 1;

    auto a_ptr = [&](int k0) -> const float* {
        int kk = k0 + kL;
        if constexpr (EPI == 0) {
            return hh + (size_t)rL * 128 + kk;
        } else {
            return (kk < 128) ? (g_aggr + (size_t)rL * 128 + kk)
                              : (hh + (size_t)rL * 128 + (kk - 128));
        }
    };

    float acc[8][8];
#pragma unroll
    for (int i = 0; i < 8; i++)
#pragma unroll
        for (int j = 0; j < 8; j++) acc[i][j] = 0.f;

    float4 pa0 = *(const float4*)(a_ptr(0));
    float4 pa1 = *(const float4*)(a_ptr(0) + 4);
    const float* wsrc = W1 + (size_t)ty * 128 + mycol;
    float4 pb0 = *(const float4*)(wsrc);
    float4 pb1 = *(const float4*)(wsrc + 4);

#pragma unroll 1
    for (int k0 = 0; k0 < DIN; k0 += 16) {
        As[(kL + 0) * 128 + rowL] = pa0.x;
        As[(kL + 1) * 128 + rowL] = pa0.y;
        As[(kL + 2) * 128 + rowL] = pa0.z;
        As[(kL + 3) * 128 + rowL] = pa0.w;
        As[(kL + 4) * 128 + rowL] = pa1.x;
        As[(kL + 5) * 128 + rowL] = pa1.y;
        As[(kL + 6) * 128 + rowL] = pa1.z;
        As[(kL + 7) * 128 + rowL] = pa1.w;
        *(float4*)(Bs + ty * 128 + mycol)     = pb0;
        *(float4*)(Bs + ty * 128 + mycol + 4) = pb1;
        __syncthreads();

        if (k0 + 16 < DIN) {
            pa0 = *(const float4*)(a_ptr(k0 + 16));
            pa1 = *(const float4*)(a_ptr(k0 + 16) + 4);
            const float* ws = W1 + (size_t)(k0 + 16 + ty) * 128 + mycol;
            pb0 = *(const float4*)(ws);
            pb1 = *(const float4*)(ws + 4);
        }
#pragma unroll
        for (int k = 0; k < 16; k++) {
            float4 a0 = *(float4*)(As + k * 128 + myrow);
            float4 a1 = *(float4*)(As + k * 128 + myrow + 4);
            float4 b0 = *(float4*)(Bs + k * 128 + mycol);
            float4 b1 = *(float4*)(Bs + k * 128 + mycol + 4);
            float a[8] = {a0.x, a0.y, a0.z, a0.w, a1.x, a1.y, a1.z, a1.w};
            float b[8] = {b0.x, b0.y, b0.z, b0.w, b1.x, b1.y, b1.z, b1.w};
#pragma unroll
            for (int i = 0; i < 8; i++)
#pragma unroll
                for (int j = 0; j < 8; j++)
                    acc[i][j] += a[i] * b[j];
        }
        __syncthreads();
    }

    {
        float gv[8], bev[8], b1v[8];
#pragma unroll
        for (int j = 0; j < 8; j++) {
            gv[j] = G[mycol + j]; bev[j] = BE[mycol + j]; b1v[j] = B1[mycol + j];
        }
#pragma unroll
        for (int i = 0; i < 8; i++) {
            float s = 0.f;
#pragma unroll
            for (int j = 0; j < 8; j++) { acc[i][j] += b1v[j]; s += acc[i][j]; }
            s += __shfl_xor_sync(0xffffffffu, s, 1);
            s += __shfl_xor_sync(0xffffffffu, s, 2);
            s += __shfl_xor_sync(0xffffffffu, s, 4);
            s += __shfl_xor_sync(0xffffffffu, s, 8);
            float mu = s * 0.0078125f;
            float s2 = 0.f;
#pragma unroll
            for (int j = 0; j < 8; j++) { float d = acc[i][j] - mu; s2 += d * d; }
            s2 += __shfl_xor_sync(0xffffffffu, s2, 1);
            s2 += __shfl_xor_sync(0xffffffffu, s2, 2);
            s2 += __shfl_xor_sync(0xffffffffu, s2, 4);
            s2 += __shfl_xor_sync(0xffffffffu, s2, 8);
            float rs = rsqrtf(s2 * 0.0078125f + 1e-5f);
#pragma unroll
            for (int j = 0; j < 8; j++)
                Hs[(myrow + i) * HSTR + mycol + j] =
                    fmaxf((acc[i][j] - mu) * rs * gv[j] + bev[j], 0.f);
        }
    }
    __syncthreads();

    float ac2[8][8];
#pragma unroll
    for (int i = 0; i < 8; i++)
#pragma unroll
        for (int j = 0; j < 8; j++) ac2[i][j] = 0.f;

    {
        const float* ws = W2 + (size_t)ty * 128 + mycol;
        pb0 = *(const float4*)(ws);
        pb1 = *(const float4*)(ws + 4);
    }
#pragma unroll 1
    for (int k0 = 0; k0 < 128; k0 += 16) {
        *(float4*)(Bs + ty * 128 + mycol)     = pb0;
        *(float4*)(Bs + ty * 128 + mycol + 4) = pb1;
        __syncthreads();
        if (k0 + 16 < 128) {
            const float* ws = W2 + (size_t)(k0 + 16 + ty) * 128 + mycol;
            pb0 = *(const float4*)(ws);
            pb1 = *(const float4*)(ws + 4);
        }
#pragma unroll
        for (int kb = 0; kb < 16; kb += 2) {
            float2 av[8];
#pragma unroll
            for (int i = 0; i < 8; i++)
                av[i] = *(float2*)(Hs + (myrow + i) * HSTR + k0 + kb);
#pragma unroll
            for (int kk = 0; kk < 2; kk++) {
                int k = kb + kk;
                float4 b0 = *(float4*)(Bs + k * 128 + mycol);
                float4 b1 = *(float4*)(Bs + k * 128 + mycol + 4);
                float b[8] = {b0.x, b0.y, b0.z, b0.w, b1.x, b1.y, b1.z, b1.w};
#pragma unroll
                for (int i = 0; i < 8; i++) {
                    float a = kk ? av[i].y : av[i].x;
#pragma unroll
                    for (int j = 0; j < 8; j++)
                        ac2[i][j] += a * b[j];
                }
            }
        }
        __syncthreads();
    }
#pragma unroll
    for (int j = 0; j < 8; j++) {
        float b2v = B2[mycol + j];
#pragma unroll
        for (int i = 0; i < 8; i++) ac2[i][j] += b2v;
    }

    float* dst0 = (EPI == 0) ? g_q : outp;
#pragma unroll
    for (int i = 0; i < 8; i++) {
        int r = row0 + myrow + i;
        if (r < nrows) {
            *(float4*)(dst0 + (size_t)r * 128 + mycol) =
                make_float4(ac2[i][0], ac2[i][1], ac2[i][2], ac2[i][3]);
            *(float4*)(dst0 + (size_t)r * 128 + mycol + 4) =
                make_float4(ac2[i][4], ac2[i][5], ac2[i][6], ac2[i][7]);
        }
    }
}

static const int NODE_SMEM = (32 * 128 + 128 * HSTR) * 4;

extern "C" void kernel_launch(void* const* d_in, const int* in_sizes, int n_in,
                              void* d_out, int out_size)
{
    const float* hPtr = (const float*)d_in[0];
    const float* ef   = (const float*)d_in[1];
    const float* ew   = (const float*)d_in[2];
    const void*  eidx = (const void*)d_in[3];
    const float* hk[6], *hv[6], *hq[6], *no[6];
    for (int i = 0; i < 6; i++) {
        hk[i] = (const float*)d_in[4 + i];
        hv[i] = (const float*)d_in[10 + i];
        hq[i] = (const float*)d_in[16 + i];
        no[i] = (const float*)d_in[22 + i];
    }
    float* outp = (float*)d_out;

    cudaFuncSetAttribute(fused_mlp<128, 0>, cudaFuncAttributeMaxDynamicSharedMemorySize, NODE_SMEM);
    cudaFuncSetAttribute(fused_mlp<256, 3>, cudaFuncAttributeMaxDynamicSharedMemorySize, NODE_SMEM);
    cudaFuncSetAttribute(edge_mlp<1, 0>, cudaFuncAttributeMaxDynamicSharedMemorySize, EDGE_SMEM);
    cudaFuncSetAttribute(edge_mlp<2, 1>, cudaFuncAttributeMaxDynamicSharedMemorySize, EDGE_SMEM);

    const int nodeBlocks = (NN + 127) / 128;
    const int edgeBlocks = EE / 128;                   // 6250
    const int flatBlocks = (NN * 128 + 255) / 256;
    const int idxBlocks  = (EE + 255) / 256;
    const int prepBlocks = (EE * 64 / 8 + NN * 128 / 8 + 255) / 256;

    detect_idx_kernel<<<1, 32>>>((const unsigned*)eidx);
    convert_idx_kernel<<<idxBlocks, 256>>>(eidx);
    prep_w<<<56, 256>>>(hk[0], hk[4], hv[0], hv[4]);
    prep_in<<<prepBlocks, 256>>>(ef, hPtr);
    init_kernel<<<flatBlocks, 256>>>();

    // q = MLP_hq(h)
    fused_mlp<128, 0><<<nodeBlocks, 256, NODE_SMEM>>>(
        hPtr, hq[0], hq[1], hq[2], hq[3], hq[4], hq[5], nullptr, NN);

    // k-MLP + logits + den (fp16 mma.sync)
    edge_mlp<1, 0><<<edgeBlocks, 256, EDGE_SMEM>>>(
        nullptr, hk[1], hk[2], hk[3], hk[5]);

    // v-MLP + alpha*e_w*v scatter (fp16 mma.sync)
    edge_mlp<2, 1><<<edgeBlocks, 256, EDGE_SMEM>>>(
        ew, hv[1], hv[2], hv[3], hv[5]);

    // out = MLP_no([aggr | h])
    fused_mlp<256, 3><<<nodeBlocks, 256, NODE_SMEM>>>(
        hPtr, no[0], no[1], no[2], no[3], no[4], no[5], outp, NN);
}

// round 9
// speedup vs baseline: 7.7250x; 1.4604x over previous
#include <cuda_runtime.h>
#include <cuda_fp16.h>
#include <cstdint>

#define NN 50000
#define EE 800000

// ---------------- scratch (device globals — allocation-free) ----------------
__device__ float    g_q[NN * 128];
__device__ float    g_logits[EE * 8];
__device__ float    g_den[NN * 8];
__device__ float    g_aggr[NN * 128];
__device__ int      g_src[EE];
__device__ int      g_dst[EE];
__device__ int      g_is64;
// fp16, SW64-swizzled weight tiles, 8KB each ([n 0..127][k32], 64B rows):
// hk: 0..13 (W1 x10, W2 x4) | hv: 14..27 | hq: 28..35 (W1 x4, W2 x4) | no: 36..47 (W1 x8, W2 x4)
__device__ char     g_wt[48 * 8192];
// fp16 inputs, row-major
__device__ __align__(16) __half g_ef[(size_t)EE * 64];
__device__ __align__(16) __half g_h[(size_t)NN * 128];
__device__ __align__(16) __half g_ag[(size_t)NN * 128];

// ======================= PTX helpers (base-target safe) =======================
__device__ __forceinline__ uint32_t smem_u32(const void* p) {
    uint32_t a;
    asm("{ .reg .u64 t; cvta.to.shared.u64 t, %1; cvt.u32.u64 %0, t; }" : "=r"(a) : "l"(p));
    return a;
}
__device__ __forceinline__ void cpa16(uint32_t dst, const void* src) {
    asm volatile("cp.async.cg.shared.global [%0], [%1], 16;" :: "r"(dst), "l"(src) : "memory");
}
#define CPA_COMMIT() asm volatile("cp.async.commit_group;" ::: "memory")
#define CPA_WAIT(n)  asm volatile("cp.async.wait_group %0;" :: "n"(n) : "memory")

__device__ __forceinline__ void ldsm4(uint32_t* r, uint32_t addr) {
    asm volatile("ldmatrix.sync.aligned.m8n8.x4.shared.b16 {%0,%1,%2,%3}, [%4];"
                 : "=r"(r[0]), "=r"(r[1]), "=r"(r[2]), "=r"(r[3]) : "r"(addr));
}
__device__ __forceinline__ void mma_f16(float* c, const uint32_t* a, uint32_t b0, uint32_t b1) {
    asm volatile("mma.sync.aligned.m16n8k16.row.col.f32.f16.f16.f32 "
                 "{%0,%1,%2,%3}, {%4,%5,%6,%7}, {%8,%9}, {%0,%1,%2,%3};"
                 : "+f"(c[0]), "+f"(c[1]), "+f"(c[2]), "+f"(c[3])
                 : "r"(a[0]), "r"(a[1]), "r"(a[2]), "r"(a[3]), "r"(b0), "r"(b1));
}

#define SW64(o) ((o) ^ (((o) >> 3) & 0x30))

__device__ __forceinline__ unsigned packh2(float a, float b) {
    __half2 t = __floats2half2_rn(a, b);
    return *reinterpret_cast<unsigned*>(&t);
}
__device__ __forceinline__ uint4 packh8(const float* x) {
    return make_uint4(packh2(x[0], x[1]), packh2(x[2], x[3]),
                      packh2(x[4], x[5]), packh2(x[6], x[7]));
}

// =================== setup kernels ===================
__global__ void detect_idx_kernel(const unsigned* __restrict__ raw) {
    if (threadIdx.x == 0 && blockIdx.x == 0) {
        int all_zero = 1;
        for (int i = 1; i < 128; i += 2)
            if (raw[i] != 0u) { all_zero = 0; break; }
        g_is64 = all_zero;
    }
}
__global__ void convert_idx_kernel(const void* __restrict__ raw) {
    int e = blockIdx.x * blockDim.x + threadIdx.x;
    if (e >= EE) return;
    if (g_is64) {
        const long long* p = (const long long*)raw;
        g_src[e] = (int)p[e];  g_dst[e] = (int)p[EE + e];
    } else {
        const int* p = (const int*)raw;
        g_src[e] = p[e];  g_dst[e] = p[EE + e];
    }
}
__global__ void init_kernel() {
    int i = blockIdx.x * blockDim.x + threadIdx.x;
    if (i < NN * 8) g_den[i] = 0.f;
    if (i < NN * 128) g_aggr[i] = 0.f;
}

// convert ef + h to fp16 (once)
__global__ void prep_in(const float* __restrict__ ef, const float* __restrict__ hh) {
    const int totEf = EE * 64 / 8;
    const int totH  = NN * 128 / 8;
    int i = blockIdx.x * blockDim.x + threadIdx.x;
    if (i < totEf) {
        float x[8];
        float4 v0 = *(const float4*)(ef + (size_t)i * 8);
        float4 v1 = *(const float4*)(ef + (size_t)i * 8 + 4);
        x[0]=v0.x; x[1]=v0.y; x[2]=v0.z; x[3]=v0.w; x[4]=v1.x; x[5]=v1.y; x[6]=v1.z; x[7]=v1.w;
        *(uint4*)(g_ef + (size_t)i * 8) = packh8(x);
    } else if (i < totEf + totH) {
        int j = i - totEf;
        float x[8];
        float4 v0 = *(const float4*)(hh + (size_t)j * 8);
        float4 v1 = *(const float4*)(hh + (size_t)j * 8 + 4);
        x[0]=v0.x; x[1]=v0.y; x[2]=v0.z; x[3]=v0.w; x[4]=v1.x; x[5]=v1.y; x[6]=v1.z; x[7]=v1.w;
        *(uint4*)(g_h + (size_t)j * 8) = packh8(x);
    }
}

// convert aggr to fp16 (after v-kernel)
__global__ void prep_ag() {
    int i = blockIdx.x * blockDim.x + threadIdx.x;
    if (i >= NN * 128 / 8) return;
    float x[8];
    float4 v0 = *(const float4*)(g_aggr + (size_t)i * 8);
    float4 v1 = *(const float4*)(g_aggr + (size_t)i * 8 + 4);
    x[0]=v0.x; x[1]=v0.y; x[2]=v0.z; x[3]=v0.w; x[4]=v1.x; x[5]=v1.y; x[6]=v1.z; x[7]=v1.w;
    *(uint4*)(g_ag + (size_t)i * 8) = packh8(x);
}

// fp16 + pre-swizzle ALL weights into 32-k SW64 tiles (transposed [n][k])
__global__ void prep_w(const float* __restrict__ k1, const float* __restrict__ k2,
                       const float* __restrict__ v1, const float* __restrict__ v2,
                       const float* __restrict__ q1, const float* __restrict__ q2,
                       const float* __restrict__ o1, const float* __restrict__ o2) {
    int idx = blockIdx.x * blockDim.x + threadIdx.x;
    if (idx >= 48 * 512) return;
    int T = idx >> 9;
    int r2 = idx & 511;
    int n = r2 >> 2, kg = r2 & 3;
    const float* W; int k0;
    if (T < 14)      { int t = T;      W = t < 10 ? k1 : k2; k0 = t < 10 ? t * 32 : (t - 10) * 32; }
    else if (T < 28) { int t = T - 14; W = t < 10 ? v1 : v2; k0 = t < 10 ? t * 32 : (t - 10) * 32; }
    else if (T < 36) { int t = T - 28; W = t < 4  ? q1 : q2; k0 = t < 4  ? t * 32 : (t - 4) * 32; }
    else             { int t = T - 36; W = t < 8  ? o1 : o2; k0 = t < 8  ? t * 32 : (t - 8) * 32; }
    float x[8];
#pragma unroll
    for (int j = 0; j < 8; j++)
        x[j] = W[(size_t)(k0 + kg * 8 + j) * 128 + n];
    *(uint4*)(g_wt + (size_t)T * 8192 + SW64(n * 64 + kg * 16)) = packh8(x);
}

// ============================================================================
// Unified fp16 mma MLP: CTA = 128 rows x 128 cols, 256 thr, warps 4(row)x2(col)
// GEMM1 (NCH 32-k chunks, double buffered) -> LN/ReLU -> H to smem tiles
// -> GEMM2 (4 chunks, N split by wc) -> epilogue.
// EPI 0: q store | 1: logits+den | 2: alpha*e_w*v scatter | 3: out store
// ============================================================================
#define OFF_W2  32768
#define OFF_PS  65536
#define OFF_PQ  66560
#define OFF_DS  67584
#define OFF_SS  68096
#define MLP_SMEM 68608

__device__ __forceinline__ void mma_chunk32(uint32_t aB, uint32_t bB,
                                            int wrRow, int wcCol, int lid,
                                            float acc[2][8][4]) {
    const int mi  = lid >> 3;
    const int rin = ((mi & 1) << 3) + (lid & 7);
    const int kh  = (mi >> 1) << 4;
    const int nin = ((mi >> 1) << 3) + (lid & 7);
    const int khb = (mi & 1) << 4;
#pragma unroll
    for (int s = 0; s < 2; s++) {
        uint32_t ah[2][4];
#pragma unroll
        for (int mt = 0; mt < 2; mt++)
            ldsm4(ah[mt], aB + SW64((wrRow + mt * 16 + rin) * 64 + s * 32 + kh));
#pragma unroll
        for (int p = 0; p < 4; p++) {
            uint32_t bh4[4];
            ldsm4(bh4, bB + SW64((wcCol + p * 16 + nin) * 64 + s * 32 + khb));
#pragma unroll
            for (int mt = 0; mt < 2; mt++)
#pragma unroll
                for (int ntl = 0; ntl < 2; ntl++)
                    mma_f16(acc[mt][p * 2 + ntl], ah[mt], bh4[ntl * 2], bh4[ntl * 2 + 1]);
        }
    }
}

template <int NCH, int MIDX, int EPI>
__global__ void __launch_bounds__(256, 2)
mlp_mma(const float* __restrict__ ew,
        const float* __restrict__ B1, const float* __restrict__ G,
        const float* __restrict__ BE, const float* __restrict__ B2,
        float* __restrict__ outp)
{
    extern __shared__ char smc[];
    const int tid = threadIdx.x;
    const int lid = tid & 31, wid = tid >> 5;
    const int wr = wid >> 1, wc = wid & 1;
    const int row0 = blockIdx.x * 128;
    uint32_t sbase = smem_u32(smc);
    int*   ds = (int*)(smc + OFF_DS);
    int*   ss = (int*)(smc + OFF_SS);
    float* pS = (float*)(smc + OFF_PS);
    float* pQ = (float*)(smc + OFF_PQ);

    if constexpr (EPI == 1 || EPI == 2) {
        if (tid < 128) { ds[tid] = g_dst[row0 + tid]; ss[tid] = g_src[row0 + tid]; }
    }

    const int arow = tid >> 1, sel = tid & 1;

    auto issueA = [&](int c) {
        const char* src;
        if constexpr (EPI == 0) {
            int rr = row0 + arow; if (rr >= NN) rr = NN - 1;
            src = (const char*)g_h + (size_t)rr * 256 + c * 64;
        } else if constexpr (EPI == 3) {
            int rr = row0 + arow; if (rr >= NN) rr = NN - 1;
            src = (c < 4) ? (const char*)g_ag + (size_t)rr * 256 + c * 64
                          : (const char*)g_h + (size_t)rr * 256 + (c - 4) * 64;
        } else {
            if (c < 2)      src = (const char*)g_ef + (size_t)(row0 + arow) * 128 + c * 64;
            else if (c < 6) src = (const char*)g_h + (size_t)ds[arow] * 256 + (c - 2) * 64;
            else            src = (const char*)g_h + (size_t)ss[arow] * 256 + (c - 6) * 64;
        }
        uint32_t ab = sbase + (c & 1) * 16384;
#pragma unroll
        for (int g = 0; g < 2; g++)
            cpa16(ab + SW64(arow * 64 + sel * 32 + g * 16), src + sel * 32 + g * 16);
    };
    auto issueB = [&](int c) {
        const char* src = g_wt + (size_t)(MIDX + c) * 8192;
        uint32_t bb = sbase + (c & 1) * 16384 + 8192;
#pragma unroll
        for (int i = 0; i < 2; i++) {
            int ix = (tid + i * 256) * 16;
            cpa16(bb + ix, src + ix);
        }
    };
    auto issueW2 = [&]() {
#pragma unroll
        for (int t = 0; t < 4; t++) {
            const char* src = g_wt + (size_t)(MIDX + NCH + t) * 8192;
            uint32_t db = sbase + OFF_W2 + t * 8192;
#pragma unroll
            for (int i = 0; i < 2; i++) {
                int ix = (tid + i * 256) * 16;
                cpa16(db + ix, src + ix);
            }
        }
    };

    float acc[2][8][4];
#pragma unroll
    for (int a = 0; a < 2; a++)
#pragma unroll
        for (int b = 0; b < 8; b++)
#pragma unroll
            for (int c = 0; c < 4; c++) acc[a][b][c] = 0.f;

    issueA(0); issueB(0); CPA_COMMIT();
    __syncthreads();                       // ds/ss visible for later chunks
    issueA(1); issueB(1); CPA_COMMIT();

    // ---------------- GEMM1: NCH chunks of 32-k ----------------
#pragma unroll 1
    for (int c = 0; c < NCH; c++) {
        CPA_WAIT(1);
        __syncthreads();
        mma_chunk32(sbase + (c & 1) * 16384, sbase + (c & 1) * 16384 + 8192,
                    wr * 32, wc * 64, lid, acc);
        __syncthreads();
        if (c + 2 < NCH)       { issueA(c + 2); issueB(c + 2); CPA_COMMIT(); }
        else if (c == NCH - 2) { issueW2(); CPA_COMMIT(); }
    }

    // ---------------- bias + LayerNorm (one pass) + ReLU ----------------
    float b1v[16], gv[16], bev[16];
#pragma unroll
    for (int nt = 0; nt < 8; nt++) {
        int col = wc * 64 + nt * 8 + 2 * (lid & 3);
        float2 t0 = *(const float2*)(B1 + col);
        float2 t1 = *(const float2*)(G + col);
        float2 t2 = *(const float2*)(BE + col);
        b1v[nt * 2] = t0.x; b1v[nt * 2 + 1] = t0.y;
        gv[nt * 2]  = t1.x; gv[nt * 2 + 1]  = t1.y;
        bev[nt * 2] = t2.x; bev[nt * 2 + 1] = t2.y;
    }
#pragma unroll
    for (int mt = 0; mt < 2; mt++)
#pragma unroll
        for (int rh = 0; rh < 2; rh++) {
            float sv = 0.f, qv = 0.f;
#pragma unroll
            for (int nt = 0; nt < 8; nt++) {
                float x0 = acc[mt][nt][rh * 2]     + b1v[nt * 2];
                float x1 = acc[mt][nt][rh * 2 + 1] + b1v[nt * 2 + 1];
                acc[mt][nt][rh * 2] = x0; acc[mt][nt][rh * 2 + 1] = x1;
                sv += x0 + x1;
                qv += x0 * x0 + x1 * x1;
            }
            sv += __shfl_xor_sync(0xffffffffu, sv, 1);
            sv += __shfl_xor_sync(0xffffffffu, sv, 2);
            qv += __shfl_xor_sync(0xffffffffu, qv, 1);
            qv += __shfl_xor_sync(0xffffffffu, qv, 2);
            if ((lid & 3) == 0) {
                int rl = wr * 32 + mt * 16 + rh * 8 + (lid >> 2);
                pS[rl * 2 + wc] = sv;
                pQ[rl * 2 + wc] = qv;
            }
        }
    __syncthreads();   // also: all GEMM1 buffer reads complete -> safe to overwrite with H

    // normalize + relu + pack fp16 -> H tiles in smem (reuse GEMM1 buffers)
#pragma unroll
    for (int mt = 0; mt < 2; mt++)
#pragma unroll
        for (int rh = 0; rh < 2; rh++) {
            int rl = wr * 32 + mt * 16 + rh * 8 + (lid >> 2);
            float mu = (pS[rl * 2] + pS[rl * 2 + 1]) * 0.0078125f;
            float var = (pQ[rl * 2] + pQ[rl * 2 + 1]) * 0.0078125f - mu * mu;
            float rs = rsqrtf(var + 1e-5f);
#pragma unroll
            for (int nt = 0; nt < 8; nt++) {
                float v0 = fmaxf((acc[mt][nt][rh * 2]     - mu) * rs * gv[nt * 2]     + bev[nt * 2], 0.f);
                float v1 = fmaxf((acc[mt][nt][rh * 2 + 1] - mu) * rs * gv[nt * 2 + 1] + bev[nt * 2 + 1], 0.f);
                int col = wc * 64 + nt * 8 + 2 * (lid & 3);
                uint32_t off = (uint32_t)(col >> 5) * 8192 + SW64(rl * 64 + (col & 31) * 2);
                *(uint32_t*)(smc + off) = packh2(v0, v1);
            }
        }

    CPA_WAIT(0);
    __syncthreads();   // H + W2 resident

    // ---------------- GEMM2: 4 chunks, full N per warp-column ----------------
    float acc2[2][8][4];
#pragma unroll
    for (int a = 0; a < 2; a++)
#pragma unroll
        for (int b = 0; b < 8; b++)
#pragma unroll
            for (int c = 0; c < 4; c++) acc2[a][b][c] = 0.f;
#pragma unroll
    for (int ch = 0; ch < 4; ch++)
        mma_chunk32(sbase + ch * 8192, sbase + OFF_W2 + ch * 8192,
                    wr * 32, wc * 64, lid, acc2);

    // bias2
#pragma unroll
    for (int nt = 0; nt < 8; nt++) {
        float2 t = *(const float2*)(B2 + wc * 64 + nt * 8 + 2 * (lid & 3));
#pragma unroll
        for (int mt = 0; mt < 2; mt++) {
            acc2[mt][nt][0] += t.x; acc2[mt][nt][1] += t.y;
            acc2[mt][nt][2] += t.x; acc2[mt][nt][3] += t.y;
        }
    }

    // ---------------- epilogues ----------------
#pragma unroll
    for (int mt = 0; mt < 2; mt++)
#pragma unroll
        for (int rh = 0; rh < 2; rh++) {
            int rl = wr * 32 + mt * 16 + rh * 8 + (lid >> 2);
            int r  = row0 + rl;
            if constexpr (EPI == 0 || EPI == 3) {
                if (r < NN) {
                    float* dst = (EPI == 0) ? g_q : outp;
#pragma unroll
                    for (int nt = 0; nt < 8; nt++)
                        *(float2*)(dst + (size_t)r * 128 + wc * 64 + nt * 8 + 2 * (lid & 3)) =
                            make_float2(acc2[mt][nt][rh * 2], acc2[mt][nt][rh * 2 + 1]);
                }
            } else if constexpr (EPI == 1) {
                int d = ds[rl];
#pragma unroll
                for (int hl = 0; hl < 4; hl++) {
                    float part = 0.f;
#pragma unroll
                    for (int jj = 0; jj < 2; jj++) {
                        int nt = hl * 2 + jj;
                        float2 q2 = *(const float2*)(g_q + (size_t)d * 128 + wc * 64 + nt * 8 + 2 * (lid & 3));
                        part += acc2[mt][nt][rh * 2] * q2.x + acc2[mt][nt][rh * 2 + 1] * q2.y;
                    }
                    part += __shfl_xor_sync(0xffffffffu, part, 1);
                    part += __shfl_xor_sync(0xffffffffu, part, 2);
                    if ((lid & 3) == 0) {
                        int hd = wc * 4 + hl;
                        float lg = part * 0.25f;
                        g_logits[(size_t)r * 8 + hd] = lg;
                        atomicAdd(&g_den[d * 8 + hd], __expf(lg));
                    }
                }
            } else {  // EPI == 2
                int d = ds[rl];
                float eww = ew[r];
#pragma unroll
                for (int hl = 0; hl < 4; hl++) {
                    int hd = wc * 4 + hl;
                    float sc = __expf(g_logits[(size_t)r * 8 + hd]) / g_den[d * 8 + hd] * eww;
#pragma unroll
                    for (int jj = 0; jj < 2; jj++) {
                        int nt = hl * 2 + jj;
                        float* op = g_aggr + (size_t)d * 128 + wc * 64 + nt * 8 + 2 * (lid & 3);
                        asm volatile("red.global.add.v2.f32 [%0], {%1,%2};" ::
                            "l"(op), "f"(acc2[mt][nt][rh * 2] * sc),
                                     "f"(acc2[mt][nt][rh * 2 + 1] * sc) : "memory");
                    }
                }
            }
        }
}

extern "C" void kernel_launch(void* const* d_in, const int* in_sizes, int n_in,
                              void* d_out, int out_size)
{
    const float* hPtr = (const float*)d_in[0];
    const float* ef   = (const float*)d_in[1];
    const float* ew   = (const float*)d_in[2];
    const void*  eidx = (const void*)d_in[3];
    const float* hk[6], *hv[6], *hq[6], *no[6];
    for (int i = 0; i < 6; i++) {
        hk[i] = (const float*)d_in[4 + i];
        hv[i] = (const float*)d_in[10 + i];
        hq[i] = (const float*)d_in[16 + i];
        no[i] = (const float*)d_in[22 + i];
    }
    float* outp = (float*)d_out;

    cudaFuncSetAttribute(mlp_mma<4, 28, 0>, cudaFuncAttributeMaxDynamicSharedMemorySize, MLP_SMEM);
    cudaFuncSetAttribute(mlp_mma<10, 0, 1>, cudaFuncAttributeMaxDynamicSharedMemorySize, MLP_SMEM);
    cudaFuncSetAttribute(mlp_mma<10, 14, 2>, cudaFuncAttributeMaxDynamicSharedMemorySize, MLP_SMEM);
    cudaFuncSetAttribute(mlp_mma<8, 36, 3>, cudaFuncAttributeMaxDynamicSharedMemorySize, MLP_SMEM);

    const int nodeBlocks = (NN + 127) / 128;           // 391
    const int edgeBlocks = EE / 128;                   // 6250
    const int flatBlocks = (NN * 128 + 255) / 256;
    const int idxBlocks  = (EE + 255) / 256;
    const int prepBlocks = (EE * 64 / 8 + NN * 128 / 8 + 255) / 256;
    const int agBlocks   = (NN * 128 / 8 + 255) / 256;

    detect_idx_kernel<<<1, 32>>>((const unsigned*)eidx);
    convert_idx_kernel<<<idxBlocks, 256>>>(eidx);
    prep_w<<<96, 256>>>(hk[0], hk[4], hv[0], hv[4], hq[0], hq[4], no[0], no[4]);
    prep_in<<<prepBlocks, 256>>>(ef, hPtr);
    init_kernel<<<flatBlocks, 256>>>();

    // q = MLP_hq(h)
    mlp_mma<4, 28, 0><<<nodeBlocks, 256, MLP_SMEM>>>(
        nullptr, hq[1], hq[2], hq[3], hq[5], nullptr);

    // k-MLP + logits + den
    mlp_mma<10, 0, 1><<<edgeBlocks, 256, MLP_SMEM>>>(
        nullptr, hk[1], hk[2], hk[3], hk[5], nullptr);

    // v-MLP + alpha*e_w*v scatter
    mlp_mma<10, 14, 2><<<edgeBlocks, 256, MLP_SMEM>>>(
        ew, hv[1], hv[2], hv[3], hv[5], nullptr);

    // aggr -> fp16
    prep_ag<<<agBlocks, 256>>>();

    // out = MLP_no([aggr | h])
    mlp_mma<8, 36, 3><<<nodeBlocks, 256, MLP_SMEM>>>(
        nullptr, no[1], no[2], no[3], no[5], outp);
}

// round 10
// speedup vs baseline: 7.9941x; 1.0348x over previous
#include <cuda_runtime.h>
#include <cuda_fp16.h>
#include <cstdint>

#define NN 50000
#define EE 800000

// ---------------- scratch (device globals — allocation-free) ----------------
__device__ float    g_q[NN * 128];
__device__ float    g_logits[EE * 8];
__device__ float    g_den[NN * 8];
__device__ float    g_aggr[NN * 128];
__device__ int      g_src[EE];
__device__ int      g_dst[EE];
__device__ int      g_is64;
// fp16, SW64-swizzled weight tiles, 8KB each ([n 0..127][k32], 64B rows):
// hk: 0..13 (W1 x10, W2 x4) | hv: 14..27 | hq: 28..35 (W1 x4, W2 x4) | no: 36..47 (W1 x8, W2 x4)
__device__ char     g_wt[48 * 8192];
// fp16 inputs, row-major
__device__ __align__(16) __half g_ef[(size_t)EE * 64];
__device__ __align__(16) __half g_h[(size_t)NN * 128];
__device__ __align__(16) __half g_ag[(size_t)NN * 128];

// ======================= PTX helpers (base-target safe) =======================
__device__ __forceinline__ uint32_t smem_u32(const void* p) {
    uint32_t a;
    asm("{ .reg .u64 t; cvta.to.shared.u64 t, %1; cvt.u32.u64 %0, t; }" : "=r"(a) : "l"(p));
    return a;
}
__device__ __forceinline__ void cpa16(uint32_t dst, const void* src) {
    asm volatile("cp.async.cg.shared.global [%0], [%1], 16;" :: "r"(dst), "l"(src) : "memory");
}
#define CPA_COMMIT() asm volatile("cp.async.commit_group;" ::: "memory")
#define CPA_WAIT(n)  asm volatile("cp.async.wait_group %0;" :: "n"(n) : "memory")

__device__ __forceinline__ void ldsm4(uint32_t* r, uint32_t addr) {
    asm volatile("ldmatrix.sync.aligned.m8n8.x4.shared.b16 {%0,%1,%2,%3}, [%4];"
                 : "=r"(r[0]), "=r"(r[1]), "=r"(r[2]), "=r"(r[3]) : "r"(addr));
}
__device__ __forceinline__ void mma_f16(float* c, const uint32_t* a, uint32_t b0, uint32_t b1) {
    asm volatile("mma.sync.aligned.m16n8k16.row.col.f32.f16.f16.f32 "
                 "{%0,%1,%2,%3}, {%4,%5,%6,%7}, {%8,%9}, {%0,%1,%2,%3};"
                 : "+f"(c[0]), "+f"(c[1]), "+f"(c[2]), "+f"(c[3])
                 : "r"(a[0]), "r"(a[1]), "r"(a[2]), "r"(a[3]), "r"(b0), "r"(b1));
}

#define SW64(o) ((o) ^ (((o) >> 3) & 0x30))

__device__ __forceinline__ unsigned packh2(float a, float b) {
    __half2 t = __floats2half2_rn(a, b);
    return *reinterpret_cast<unsigned*>(&t);
}
__device__ __forceinline__ uint4 packh8(const float* x) {
    return make_uint4(packh2(x[0], x[1]), packh2(x[2], x[3]),
                      packh2(x[4], x[5]), packh2(x[6], x[7]));
}

// =================== setup kernels ===================
__global__ void detect_idx_kernel(const unsigned* __restrict__ raw) {
    if (threadIdx.x == 0 && blockIdx.x == 0) {
        int all_zero = 1;
        for (int i = 1; i < 128; i += 2)
            if (raw[i] != 0u) { all_zero = 0; break; }
        g_is64 = all_zero;
    }
}
__global__ void convert_idx_kernel(const void* __restrict__ raw) {
    int e = blockIdx.x * blockDim.x + threadIdx.x;
    if (e >= EE) return;
    if (g_is64) {
        const long long* p = (const long long*)raw;
        g_src[e] = (int)p[e];  g_dst[e] = (int)p[EE + e];
    } else {
        const int* p = (const int*)raw;
        g_src[e] = p[e];  g_dst[e] = p[EE + e];
    }
}
__global__ void init_kernel() {
    int i = blockIdx.x * blockDim.x + threadIdx.x;
    if (i < NN * 8) g_den[i] = 0.f;
    if (i < NN * 128) g_aggr[i] = 0.f;
}

// convert ef + h to fp16 (once)
__global__ void prep_in(const float* __restrict__ ef, const float* __restrict__ hh) {
    const int totEf = EE * 64 / 8;
    const int totH  = NN * 128 / 8;
    int i = blockIdx.x * blockDim.x + threadIdx.x;
    if (i < totEf) {
        float x[8];
        float4 v0 = *(const float4*)(ef + (size_t)i * 8);
        float4 v1 = *(const float4*)(ef + (size_t)i * 8 + 4);
        x[0]=v0.x; x[1]=v0.y; x[2]=v0.z; x[3]=v0.w; x[4]=v1.x; x[5]=v1.y; x[6]=v1.z; x[7]=v1.w;
        *(uint4*)(g_ef + (size_t)i * 8) = packh8(x);
    } else if (i < totEf + totH) {
        int j = i - totEf;
        float x[8];
        float4 v0 = *(const float4*)(hh + (size_t)j * 8);
        float4 v1 = *(const float4*)(hh + (size_t)j * 8 + 4);
        x[0]=v0.x; x[1]=v0.y; x[2]=v0.z; x[3]=v0.w; x[4]=v1.x; x[5]=v1.y; x[6]=v1.z; x[7]=v1.w;
        *(uint4*)(g_h + (size_t)j * 8) = packh8(x);
    }
}

// convert aggr to fp16 (after v-kernel)
__global__ void prep_ag() {
    int i = blockIdx.x * blockDim.x + threadIdx.x;
    if (i >= NN * 128 / 8) return;
    float x[8];
    float4 v0 = *(const float4*)(g_aggr + (size_t)i * 8);
    float4 v1 = *(const float4*)(g_aggr + (size_t)i * 8 + 4);
    x[0]=v0.x; x[1]=v0.y; x[2]=v0.z; x[3]=v0.w; x[4]=v1.x; x[5]=v1.y; x[6]=v1.z; x[7]=v1.w;
    *(uint4*)(g_ag + (size_t)i * 8) = packh8(x);
}

// fp16 + pre-swizzle ALL weights into 32-k SW64 tiles (transposed [n][k])
__global__ void prep_w(const float* __restrict__ k1, const float* __restrict__ k2,
                       const float* __restrict__ v1, const float* __restrict__ v2,
                       const float* __restrict__ q1, const float* __restrict__ q2,
                       const float* __restrict__ o1, const float* __restrict__ o2) {
    int idx = blockIdx.x * blockDim.x + threadIdx.x;
    if (idx >= 48 * 512) return;
    int T = idx >> 9;
    int r2 = idx & 511;
    int n = r2 >> 2, kg = r2 & 3;
    const float* W; int k0;
    if (T < 14)      { int t = T;      W = t < 10 ? k1 : k2; k0 = t < 10 ? t * 32 : (t - 10) * 32; }
    else if (T < 28) { int t = T - 14; W = t < 10 ? v1 : v2; k0 = t < 10 ? t * 32 : (t - 10) * 32; }
    else if (T < 36) { int t = T - 28; W = t < 4  ? q1 : q2; k0 = t < 4  ? t * 32 : (t - 4) * 32; }
    else             { int t = T - 36; W = t < 8  ? o1 : o2; k0 = t < 8  ? t * 32 : (t - 8) * 32; }
    float x[8];
#pragma unroll
    for (int j = 0; j < 8; j++)
        x[j] = W[(size_t)(k0 + kg * 8 + j) * 128 + n];
    *(uint4*)(g_wt + (size_t)T * 8192 + SW64(n * 64 + kg * 16)) = packh8(x);
}

// ============================================================================
// Unified fp16 mma MLP: CTA = 128 rows x 128 cols, 256 thr, warps 4(row)x2(col)
// GEMM1: NCH 32-k chunks, 3-stage cp.async pipeline, ONE sync per iteration.
// -> LN/ReLU -> H to smem tiles (reuse buffers) -> GEMM2 (4 chunks) -> epilogue
// EPI 0: q store | 1: logits+den | 2: alpha*e_w*v scatter | 3: out store
// ============================================================================
#define OFF_W2  49152
#define OFF_PS  81920
#define OFF_PQ  82944
#define OFF_DS  83968
#define OFF_SS  84480
#define MLP_SMEM 84992

__device__ __forceinline__ void mma_chunk32(uint32_t aB, uint32_t bB,
                                            int wrRow, int wcCol, int lid,
                                            float acc[2][8][4]) {
    const int mi  = lid >> 3;
    const int rin = ((mi & 1) << 3) + (lid & 7);
    const int kh  = (mi >> 1) << 4;
    const int nin = ((mi >> 1) << 3) + (lid & 7);
    const int khb = (mi & 1) << 4;
#pragma unroll
    for (int s = 0; s < 2; s++) {
        uint32_t ah[2][4];
#pragma unroll
        for (int mt = 0; mt < 2; mt++)
            ldsm4(ah[mt], aB + SW64((wrRow + mt * 16 + rin) * 64 + s * 32 + kh));
#pragma unroll
        for (int p = 0; p < 4; p++) {
            uint32_t bh4[4];
            ldsm4(bh4, bB + SW64((wcCol + p * 16 + nin) * 64 + s * 32 + khb));
#pragma unroll
            for (int mt = 0; mt < 2; mt++)
#pragma unroll
                for (int ntl = 0; ntl < 2; ntl++)
                    mma_f16(acc[mt][p * 2 + ntl], ah[mt], bh4[ntl * 2], bh4[ntl * 2 + 1]);
        }
    }
}

template <int NCH, int MIDX, int EPI>
__global__ void __launch_bounds__(256, 2)
mlp_mma(const float* __restrict__ ew,
        const float* __restrict__ B1, const float* __restrict__ G,
        const float* __restrict__ BE, const float* __restrict__ B2,
        float* __restrict__ outp)
{
    extern __shared__ char smc[];
    const int tid = threadIdx.x;
    const int lid = tid & 31, wid = tid >> 5;
    const int wr = wid >> 1, wc = wid & 1;
    const int row0 = blockIdx.x * 128;
    uint32_t sbase = smem_u32(smc);
    int*   ds = (int*)(smc + OFF_DS);
    int*   ss = (int*)(smc + OFF_SS);
    float* pS = (float*)(smc + OFF_PS);
    float* pQ = (float*)(smc + OFF_PQ);

    if constexpr (EPI == 1 || EPI == 2) {
        if (tid < 128) { ds[tid] = g_dst[row0 + tid]; ss[tid] = g_src[row0 + tid]; }
    }

    const int arow = tid >> 1, sel = tid & 1;

    auto issueA = [&](int c) {
        const char* src;
        if constexpr (EPI == 0) {
            int rr = row0 + arow; if (rr >= NN) rr = NN - 1;
            src = (const char*)g_h + (size_t)rr * 256 + c * 64;
        } else if constexpr (EPI == 3) {
            int rr = row0 + arow; if (rr >= NN) rr = NN - 1;
            src = (c < 4) ? (const char*)g_ag + (size_t)rr * 256 + c * 64
                          : (const char*)g_h + (size_t)rr * 256 + (c - 4) * 64;
        } else {
            if (c < 2)      src = (const char*)g_ef + (size_t)(row0 + arow) * 128 + c * 64;
            else if (c < 6) src = (const char*)g_h + (size_t)ds[arow] * 256 + (c - 2) * 64;
            else            src = (const char*)g_h + (size_t)ss[arow] * 256 + (c - 6) * 64;
        }
        uint32_t ab = sbase + (c % 3) * 16384;
#pragma unroll
        for (int g = 0; g < 2; g++)
            cpa16(ab + SW64(arow * 64 + sel * 32 + g * 16), src + sel * 32 + g * 16);
    };
    auto issueB = [&](int c) {
        const char* src = g_wt + (size_t)(MIDX + c) * 8192;
        uint32_t bb = sbase + (c % 3) * 16384 + 8192;
#pragma unroll
        for (int i = 0; i < 2; i++) {
            int ix = (tid + i * 256) * 16;
            cpa16(bb + ix, src + ix);
        }
    };
    auto issueW2 = [&]() {
#pragma unroll
        for (int t = 0; t < 4; t++) {
            const char* src = g_wt + (size_t)(MIDX + NCH + t) * 8192;
            uint32_t db = sbase + OFF_W2 + t * 8192;
#pragma unroll
            for (int i = 0; i < 2; i++) {
                int ix = (tid + i * 256) * 16;
                cpa16(db + ix, src + ix);
            }
        }
    };

    float acc[2][8][4];
#pragma unroll
    for (int a = 0; a < 2; a++)
#pragma unroll
        for (int b = 0; b < 8; b++)
#pragma unroll
            for (int c = 0; c < 4; c++) acc[a][b][c] = 0.f;

    // prologue: chunks 0,1 use ef / clamped rows only (no ds/ss needed)
    issueA(0); issueB(0); CPA_COMMIT();
    issueA(1); issueB(1); CPA_COMMIT();

    // ---------------- GEMM1: NCH chunks, 3-stage, 1 sync/iter ----------------
#pragma unroll 1
    for (int c = 0; c < NCH; c++) {
        CPA_WAIT(1);
        __syncthreads();   // buffer c ready for all; all warps done with buffer c-1
        mma_chunk32(sbase + (c % 3) * 16384, sbase + (c % 3) * 16384 + 8192,
                    wr * 32, wc * 64, lid, acc);
        if (c + 2 < NCH)       { issueA(c + 2); issueB(c + 2); CPA_COMMIT(); }
        else if (c == NCH - 2) { issueW2(); CPA_COMMIT(); }
    }

    // ---------------- bias + LayerNorm (one pass) + ReLU ----------------
    float b1v[16], gv[16], bev[16];
#pragma unroll
    for (int nt = 0; nt < 8; nt++) {
        int col = wc * 64 + nt * 8 + 2 * (lid & 3);
        float2 t0 = *(const float2*)(B1 + col);
        float2 t1 = *(const float2*)(G + col);
        float2 t2 = *(const float2*)(BE + col);
        b1v[nt * 2] = t0.x; b1v[nt * 2 + 1] = t0.y;
        gv[nt * 2]  = t1.x; gv[nt * 2 + 1]  = t1.y;
        bev[nt * 2] = t2.x; bev[nt * 2 + 1] = t2.y;
    }
#pragma unroll
    for (int mt = 0; mt < 2; mt++)
#pragma unroll
        for (int rh = 0; rh < 2; rh++) {
            float sv = 0.f, qv = 0.f;
#pragma unroll
            for (int nt = 0; nt < 8; nt++) {
                float x0 = acc[mt][nt][rh * 2]     + b1v[nt * 2];
                float x1 = acc[mt][nt][rh * 2 + 1] + b1v[nt * 2 + 1];
                acc[mt][nt][rh * 2] = x0; acc[mt][nt][rh * 2 + 1] = x1;
                sv += x0 + x1;
                qv += x0 * x0 + x1 * x1;
            }
            sv += __shfl_xor_sync(0xffffffffu, sv, 1);
            sv += __shfl_xor_sync(0xffffffffu, sv, 2);
            qv += __shfl_xor_sync(0xffffffffu, qv, 1);
            qv += __shfl_xor_sync(0xffffffffu, qv, 2);
            if ((lid & 3) == 0) {
                int rl = wr * 32 + mt * 16 + rh * 8 + (lid >> 2);
                pS[rl * 2 + wc] = sv;
                pQ[rl * 2 + wc] = qv;
            }
        }
    __syncthreads();   // partials visible; ALL warps past final mma -> buffers reusable

    // normalize + relu + pack fp16 -> H tiles in smem (overwrite GEMM1 buffers)
#pragma unroll
    for (int mt = 0; mt < 2; mt++)
#pragma unroll
        for (int rh = 0; rh < 2; rh++) {
            int rl = wr * 32 + mt * 16 + rh * 8 + (lid >> 2);
            float mu = (pS[rl * 2] + pS[rl * 2 + 1]) * 0.0078125f;
            float var = (pQ[rl * 2] + pQ[rl * 2 + 1]) * 0.0078125f - mu * mu;
            float rs = rsqrtf(var + 1e-5f);
#pragma unroll
            for (int nt = 0; nt < 8; nt++) {
                float v0 = fmaxf((acc[mt][nt][rh * 2]     - mu) * rs * gv[nt * 2]     + bev[nt * 2], 0.f);
                float v1 = fmaxf((acc[mt][nt][rh * 2 + 1] - mu) * rs * gv[nt * 2 + 1] + bev[nt * 2 + 1], 0.f);
                int col = wc * 64 + nt * 8 + 2 * (lid & 3);
                uint32_t off = (uint32_t)(col >> 5) * 8192 + SW64(rl * 64 + (col & 31) * 2);
                *(uint32_t*)(smc + off) = packh2(v0, v1);
            }
        }

    CPA_WAIT(0);
    __syncthreads();   // H + W2 resident

    // ---------------- GEMM2: 4 chunks, full N per warp-column ----------------
    float acc2[2][8][4];
#pragma unroll
    for (int a = 0; a < 2; a++)
#pragma unroll
        for (int b = 0; b < 8; b++)
#pragma unroll
            for (int c = 0; c < 4; c++) acc2[a][b][c] = 0.f;
#pragma unroll
    for (int ch = 0; ch < 4; ch++)
        mma_chunk32(sbase + ch * 8192, sbase + OFF_W2 + ch * 8192,
                    wr * 32, wc * 64, lid, acc2);

    // bias2
#pragma unroll
    for (int nt = 0; nt < 8; nt++) {
        float2 t = *(const float2*)(B2 + wc * 64 + nt * 8 + 2 * (lid & 3));
#pragma unroll
        for (int mt = 0; mt < 2; mt++) {
            acc2[mt][nt][0] += t.x; acc2[mt][nt][1] += t.y;
            acc2[mt][nt][2] += t.x; acc2[mt][nt][3] += t.y;
        }
    }

    // ---------------- epilogues ----------------
#pragma unroll
    for (int mt = 0; mt < 2; mt++)
#pragma unroll
        for (int rh = 0; rh < 2; rh++) {
            int rl = wr * 32 + mt * 16 + rh * 8 + (lid >> 2);
            int r  = row0 + rl;
            if constexpr (EPI == 0 || EPI == 3) {
                if (r < NN) {
                    float* dst = (EPI == 0) ? g_q : outp;
#pragma unroll
                    for (int nt = 0; nt < 8; nt++)
                        *(float2*)(dst + (size_t)r * 128 + wc * 64 + nt * 8 + 2 * (lid & 3)) =
                            make_float2(acc2[mt][nt][rh * 2], acc2[mt][nt][rh * 2 + 1]);
                }
            } else if constexpr (EPI == 1) {
                int d = ds[rl];
#pragma unroll
                for (int hl = 0; hl < 4; hl++) {
                    float part = 0.f;
#pragma unroll
                    for (int jj = 0; jj < 2; jj++) {
                        int nt = hl * 2 + jj;
                        float2 q2 = *(const float2*)(g_q + (size_t)d * 128 + wc * 64 + nt * 8 + 2 * (lid & 3));
                        part += acc2[mt][nt][rh * 2] * q2.x + acc2[mt][nt][rh * 2 + 1] * q2.y;
                    }
                    part += __shfl_xor_sync(0xffffffffu, part, 1);
                    part += __shfl_xor_sync(0xffffffffu, part, 2);
                    if ((lid & 3) == 0) {
                        int hd = wc * 4 + hl;
                        float lg = part * 0.25f;
                        g_logits[(size_t)r * 8 + hd] = lg;
                        atomicAdd(&g_den[d * 8 + hd], __expf(lg));
                    }
                }
            } else {  // EPI == 2
                int d = ds[rl];
                float eww = ew[r];
#pragma unroll
                for (int hl = 0; hl < 4; hl++) {
                    int hd = wc * 4 + hl;
                    float sc = __expf(g_logits[(size_t)r * 8 + hd]) / g_den[d * 8 + hd] * eww;
#pragma unroll
                    for (int jj = 0; jj < 2; jj++) {
                        int nt = hl * 2 + jj;
                        float* op = g_aggr + (size_t)d * 128 + wc * 64 + nt * 8 + 2 * (lid & 3);
                        asm volatile("red.global.add.v2.f32 [%0], {%1,%2};" ::
                            "l"(op), "f"(acc2[mt][nt][rh * 2] * sc),
                                     "f"(acc2[mt][nt][rh * 2 + 1] * sc) : "memory");
                    }
                }
            }
        }
}

extern "C" void kernel_launch(void* const* d_in, const int* in_sizes, int n_in,
                              void* d_out, int out_size)
{
    const float* hPtr = (const float*)d_in[0];
    const float* ef   = (const float*)d_in[1];
    const float* ew   = (const float*)d_in[2];
    const void*  eidx = (const void*)d_in[3];
    const float* hk[6], *hv[6], *hq[6], *no[6];
    for (int i = 0; i < 6; i++) {
        hk[i] = (const float*)d_in[4 + i];
        hv[i] = (const float*)d_in[10 + i];
        hq[i] = (const float*)d_in[16 + i];
        no[i] = (const float*)d_in[22 + i];
    }
    float* outp = (float*)d_out;

    cudaFuncSetAttribute(mlp_mma<4, 28, 0>, cudaFuncAttributeMaxDynamicSharedMemorySize, MLP_SMEM);
    cudaFuncSetAttribute(mlp_mma<10, 0, 1>, cudaFuncAttributeMaxDynamicSharedMemorySize, MLP_SMEM);
    cudaFuncSetAttribute(mlp_mma<10, 14, 2>, cudaFuncAttributeMaxDynamicSharedMemorySize, MLP_SMEM);
    cudaFuncSetAttribute(mlp_mma<8, 36, 3>, cudaFuncAttributeMaxDynamicSharedMemorySize, MLP_SMEM);

    const int nodeBlocks = (NN + 127) / 128;           // 391
    const int edgeBlocks = EE / 128;                   // 6250
    const int flatBlocks = (NN * 128 + 255) / 256;
    const int idxBlocks  = (EE + 255) / 256;
    const int prepBlocks = (EE * 64 / 8 + NN * 128 / 8 + 255) / 256;
    const int agBlocks   = (NN * 128 / 8 + 255) / 256;

    detect_idx_kernel<<<1, 32>>>((const unsigned*)eidx);
    convert_idx_kernel<<<idxBlocks, 256>>>(eidx);
    prep_w<<<96, 256>>>(hk[0], hk[4], hv[0], hv[4], hq[0], hq[4], no[0], no[4]);
    prep_in<<<prepBlocks, 256>>>(ef, hPtr);
    init_kernel<<<flatBlocks, 256>>>();

    // q = MLP_hq(h)
    mlp_mma<4, 28, 0><<<nodeBlocks, 256, MLP_SMEM>>>(
        nullptr, hq[1], hq[2], hq[3], hq[5], nullptr);

    // k-MLP + logits + den
    mlp_mma<10, 0, 1><<<edgeBlocks, 256, MLP_SMEM>>>(
        nullptr, hk[1], hk[2], hk[3], hk[5], nullptr);

    // v-MLP + alpha*e_w*v scatter
    mlp_mma<10, 14, 2><<<edgeBlocks, 256, MLP_SMEM>>>(
        ew, hv[1], hv[2], hv[3], hv[5], nullptr);

    // aggr -> fp16
    prep_ag<<<agBlocks, 256>>>();

    // out = MLP_no([aggr | h])
    mlp_mma<8, 36, 3><<<nodeBlocks, 256, MLP_SMEM>>>(
        nullptr, no[1], no[2], no[3], no[5], outp);
}

// round 11
// speedup vs baseline: 8.0168x; 1.0028x over previous
#include <cuda_runtime.h>
#include <cuda_fp16.h>
#include <cstdint>

#define NN 50000
#define EE 800000

// ---------------- scratch (device globals — allocation-free) ----------------
__device__ float    g_q[NN * 128];
__device__ float    g_logits[EE * 8];
__device__ float    g_den[NN * 8];
__device__ float    g_aggr[NN * 128];
__device__ int      g_src[EE];
__device__ int      g_dst[EE];
__device__ int      g_is64;
// fp16, SW64-swizzled weight tiles, 8KB each ([n 0..127][k32], 64B rows):
// hk: 0..13 (W1 x10, W2 x4) | hv: 14..27 | hq: 28..35 (W1 x4, W2 x4) | no: 36..47 (W1 x8, W2 x4)
__device__ char     g_wt[48 * 8192];
// fp16 inputs, row-major
__device__ __align__(16) __half g_ef[(size_t)EE * 64];
__device__ __align__(16) __half g_h[(size_t)NN * 128];
__device__ __align__(16) __half g_ag[(size_t)NN * 128];

// ======================= PTX helpers (base-target safe) =======================
__device__ __forceinline__ uint32_t smem_u32(const void* p) {
    uint32_t a;
    asm("{ .reg .u64 t; cvta.to.shared.u64 t, %1; cvt.u32.u64 %0, t; }" : "=r"(a) : "l"(p));
    return a;
}
__device__ __forceinline__ void cpa16(uint32_t dst, const void* src) {
    asm volatile("cp.async.cg.shared.global [%0], [%1], 16;" :: "r"(dst), "l"(src) : "memory");
}
#define CPA_COMMIT() asm volatile("cp.async.commit_group;" ::: "memory")
#define CPA_WAIT(n)  asm volatile("cp.async.wait_group %0;" :: "n"(n) : "memory")

__device__ __forceinline__ void ldsm4(uint32_t* r, uint32_t addr) {
    asm volatile("ldmatrix.sync.aligned.m8n8.x4.shared.b16 {%0,%1,%2,%3}, [%4];"
                 : "=r"(r[0]), "=r"(r[1]), "=r"(r[2]), "=r"(r[3]) : "r"(addr));
}
__device__ __forceinline__ void mma_f16(float* c, const uint32_t* a, uint32_t b0, uint32_t b1) {
    asm volatile("mma.sync.aligned.m16n8k16.row.col.f32.f16.f16.f32 "
                 "{%0,%1,%2,%3}, {%4,%5,%6,%7}, {%8,%9}, {%0,%1,%2,%3};"
                 : "+f"(c[0]), "+f"(c[1]), "+f"(c[2]), "+f"(c[3])
                 : "r"(a[0]), "r"(a[1]), "r"(a[2]), "r"(a[3]), "r"(b0), "r"(b1));
}

#define SW64(o) ((o) ^ (((o) >> 3) & 0x30))

__device__ __forceinline__ unsigned packh2(float a, float b) {
    __half2 t = __floats2half2_rn(a, b);
    return *reinterpret_cast<unsigned*>(&t);
}
__device__ __forceinline__ uint4 packh8(const float* x) {
    return make_uint4(packh2(x[0], x[1]), packh2(x[2], x[3]),
                      packh2(x[4], x[5]), packh2(x[6], x[7]));
}

// =================== setup kernels ===================
__global__ void detect_idx_kernel(const unsigned* __restrict__ raw) {
    if (threadIdx.x == 0 && blockIdx.x == 0) {
        int all_zero = 1;
        for (int i = 1; i < 128; i += 2)
            if (raw[i] != 0u) { all_zero = 0; break; }
        g_is64 = all_zero;
    }
}
__global__ void convert_idx_kernel(const void* __restrict__ raw) {
    int e = blockIdx.x * blockDim.x + threadIdx.x;
    if (e >= EE) return;
    if (g_is64) {
        const long long* p = (const long long*)raw;
        g_src[e] = (int)p[e];  g_dst[e] = (int)p[EE + e];
    } else {
        const int* p = (const int*)raw;
        g_src[e] = p[e];  g_dst[e] = p[EE + e];
    }
}
__global__ void init_kernel() {
    int i = blockIdx.x * blockDim.x + threadIdx.x;
    if (i < NN * 8) g_den[i] = 0.f;
    if (i < NN * 128) g_aggr[i] = 0.f;
}

// convert ef + h to fp16 (once)
__global__ void prep_in(const float* __restrict__ ef, const float* __restrict__ hh) {
    const int totEf = EE * 64 / 8;
    const int totH  = NN * 128 / 8;
    int i = blockIdx.x * blockDim.x + threadIdx.x;
    if (i < totEf) {
        float x[8];
        float4 v0 = *(const float4*)(ef + (size_t)i * 8);
        float4 v1 = *(const float4*)(ef + (size_t)i * 8 + 4);
        x[0]=v0.x; x[1]=v0.y; x[2]=v0.z; x[3]=v0.w; x[4]=v1.x; x[5]=v1.y; x[6]=v1.z; x[7]=v1.w;
        *(uint4*)(g_ef + (size_t)i * 8) = packh8(x);
    } else if (i < totEf + totH) {
        int j = i - totEf;
        float x[8];
        float4 v0 = *(const float4*)(hh + (size_t)j * 8);
        float4 v1 = *(const float4*)(hh + (size_t)j * 8 + 4);
        x[0]=v0.x; x[1]=v0.y; x[2]=v0.z; x[3]=v0.w; x[4]=v1.x; x[5]=v1.y; x[6]=v1.z; x[7]=v1.w;
        *(uint4*)(g_h + (size_t)j * 8) = packh8(x);
    }
}

// convert aggr to fp16 (after v-kernel)
__global__ void prep_ag() {
    int i = blockIdx.x * blockDim.x + threadIdx.x;
    if (i >= NN * 128 / 8) return;
    float x[8];
    float4 v0 = *(const float4*)(g_aggr + (size_t)i * 8);
    float4 v1 = *(const float4*)(g_aggr + (size_t)i * 8 + 4);
    x[0]=v0.x; x[1]=v0.y; x[2]=v0.z; x[3]=v0.w; x[4]=v1.x; x[5]=v1.y; x[6]=v1.z; x[7]=v1.w;
    *(uint4*)(g_ag + (size_t)i * 8) = packh8(x);
}

// fp16 + pre-swizzle ALL weights into 32-k SW64 tiles (transposed [n][k])
__global__ void prep_w(const float* __restrict__ k1, const float* __restrict__ k2,
                       const float* __restrict__ v1, const float* __restrict__ v2,
                       const float* __restrict__ q1, const float* __restrict__ q2,
                       const float* __restrict__ o1, const float* __restrict__ o2) {
    int idx = blockIdx.x * blockDim.x + threadIdx.x;
    if (idx >= 48 * 512) return;
    int T = idx >> 9;
    int r2 = idx & 511;
    int n = r2 >> 2, kg = r2 & 3;
    const float* W; int k0;
    if (T < 14)      { int t = T;      W = t < 10 ? k1 : k2; k0 = t < 10 ? t * 32 : (t - 10) * 32; }
    else if (T < 28) { int t = T - 14; W = t < 10 ? v1 : v2; k0 = t < 10 ? t * 32 : (t - 10) * 32; }
    else if (T < 36) { int t = T - 28; W = t < 4  ? q1 : q2; k0 = t < 4  ? t * 32 : (t - 4) * 32; }
    else             { int t = T - 36; W = t < 8  ? o1 : o2; k0 = t < 8  ? t * 32 : (t - 8) * 32; }
    float x[8];
#pragma unroll
    for (int j = 0; j < 8; j++)
        x[j] = W[(size_t)(k0 + kg * 8 + j) * 128 + n];
    *(uint4*)(g_wt + (size_t)T * 8192 + SW64(n * 64 + kg * 16)) = packh8(x);
}

// ============================================================================
// Unified fp16 mma MLP: CTA = 128 rows x 128 cols, 256 thr, warps 4(row)x2(col)
// GEMM1: NCH 32-k chunks, 3-stage cp.async pipeline, ONE sync per iteration.
// -> LN/ReLU -> H to smem tiles (reuse buffers) -> GEMM2 (4 chunks) -> epilogue
// EPI 0: q store | 1: logits+den | 2: alpha*e_w*v scatter | 3: out store
// ============================================================================
#define OFF_W2  49152
#define OFF_PS  81920
#define OFF_PQ  82944
#define OFF_DS  83968
#define OFF_SS  84480
#define MLP_SMEM 84992

__device__ __forceinline__ void mma_chunk32(uint32_t aB, uint32_t bB,
                                            int wrRow, int wcCol, int lid,
                                            float acc[2][8][4]) {
    const int mi  = lid >> 3;
    const int rin = ((mi & 1) << 3) + (lid & 7);
    const int kh  = (mi >> 1) << 4;
    const int nin = ((mi >> 1) << 3) + (lid & 7);
    const int khb = (mi & 1) << 4;
#pragma unroll
    for (int s = 0; s < 2; s++) {
        uint32_t ah[2][4];
#pragma unroll
        for (int mt = 0; mt < 2; mt++)
            ldsm4(ah[mt], aB + SW64((wrRow + mt * 16 + rin) * 64 + s * 32 + kh));
#pragma unroll
        for (int p = 0; p < 4; p++) {
            uint32_t bh4[4];
            ldsm4(bh4, bB + SW64((wcCol + p * 16 + nin) * 64 + s * 32 + khb));
#pragma unroll
            for (int mt = 0; mt < 2; mt++)
#pragma unroll
                for (int ntl = 0; ntl < 2; ntl++)
                    mma_f16(acc[mt][p * 2 + ntl], ah[mt], bh4[ntl * 2], bh4[ntl * 2 + 1]);
        }
    }
}

template <int NCH, int MIDX, int EPI>
__global__ void __launch_bounds__(256, 2)
mlp_mma(const float* __restrict__ ew,
        const float* __restrict__ B1, const float* __restrict__ G,
        const float* __restrict__ BE, const float* __restrict__ B2,
        float* __restrict__ outp)
{
    extern __shared__ char smc[];
    const int tid = threadIdx.x;
    const int lid = tid & 31, wid = tid >> 5;
    const int wr = wid >> 1, wc = wid & 1;
    const int row0 = blockIdx.x * 128;
    uint32_t sbase = smem_u32(smc);
    int*   ds = (int*)(smc + OFF_DS);
    int*   ss = (int*)(smc + OFF_SS);
    float* pS = (float*)(smc + OFF_PS);
    float* pQ = (float*)(smc + OFF_PQ);

    if constexpr (EPI == 1 || EPI == 2) {
        if (tid < 128) { ds[tid] = g_dst[row0 + tid]; ss[tid] = g_src[row0 + tid]; }
    }

    const int arow = tid >> 1, sel = tid & 1;

    auto issueA = [&](int c) {
        const char* src;
        if constexpr (EPI == 0) {
            int rr = row0 + arow; if (rr >= NN) rr = NN - 1;
            src = (const char*)g_h + (size_t)rr * 256 + c * 64;
        } else if constexpr (EPI == 3) {
            int rr = row0 + arow; if (rr >= NN) rr = NN - 1;
            src = (c < 4) ? (const char*)g_ag + (size_t)rr * 256 + c * 64
                          : (const char*)g_h + (size_t)rr * 256 + (c - 4) * 64;
        } else {
            if (c < 2)      src = (const char*)g_ef + (size_t)(row0 + arow) * 128 + c * 64;
            else if (c < 6) src = (const char*)g_h + (size_t)ds[arow] * 256 + (c - 2) * 64;
            else            src = (const char*)g_h + (size_t)ss[arow] * 256 + (c - 6) * 64;
        }
        uint32_t ab = sbase + (c % 3) * 16384;
#pragma unroll
        for (int g = 0; g < 2; g++)
            cpa16(ab + SW64(arow * 64 + sel * 32 + g * 16), src + sel * 32 + g * 16);
    };
    auto issueB = [&](int c) {
        const char* src = g_wt + (size_t)(MIDX + c) * 8192;
        uint32_t bb = sbase + (c % 3) * 16384 + 8192;
#pragma unroll
        for (int i = 0; i < 2; i++) {
            int ix = (tid + i * 256) * 16;
            cpa16(bb + ix, src + ix);
        }
    };
    auto issueW2 = [&]() {
#pragma unroll
        for (int t = 0; t < 4; t++) {
            const char* src = g_wt + (size_t)(MIDX + NCH + t) * 8192;
            uint32_t db = sbase + OFF_W2 + t * 8192;
#pragma unroll
            for (int i = 0; i < 2; i++) {
                int ix = (tid + i * 256) * 16;
                cpa16(db + ix, src + ix);
            }
        }
    };

    float acc[2][8][4];
#pragma unroll
    for (int a = 0; a < 2; a++)
#pragma unroll
        for (int b = 0; b < 8; b++)
#pragma unroll
            for (int c = 0; c < 4; c++) acc[a][b][c] = 0.f;

    // prologue: chunks 0,1 use ef / clamped rows only (no ds/ss needed)
    issueA(0); issueB(0); CPA_COMMIT();
    issueA(1); issueB(1); CPA_COMMIT();

    // ---------------- GEMM1: NCH chunks, 3-stage, 1 sync/iter ----------------
#pragma unroll 1
    for (int c = 0; c < NCH; c++) {
        CPA_WAIT(1);
        __syncthreads();   // buffer c ready for all; all warps done with buffer c-1
        mma_chunk32(sbase + (c % 3) * 16384, sbase + (c % 3) * 16384 + 8192,
                    wr * 32, wc * 64, lid, acc);
        if (c + 2 < NCH)       { issueA(c + 2); issueB(c + 2); CPA_COMMIT(); }
        else if (c == NCH - 2) { issueW2(); CPA_COMMIT(); }
    }

    // ---------------- bias + LayerNorm (one pass) + ReLU ----------------
    float b1v[16], gv[16], bev[16];
#pragma unroll
    for (int nt = 0; nt < 8; nt++) {
        int col = wc * 64 + nt * 8 + 2 * (lid & 3);
        float2 t0 = *(const float2*)(B1 + col);
        float2 t1 = *(const float2*)(G + col);
        float2 t2 = *(const float2*)(BE + col);
        b1v[nt * 2] = t0.x; b1v[nt * 2 + 1] = t0.y;
        gv[nt * 2]  = t1.x; gv[nt * 2 + 1]  = t1.y;
        bev[nt * 2] = t2.x; bev[nt * 2 + 1] = t2.y;
    }
#pragma unroll
    for (int mt = 0; mt < 2; mt++)
#pragma unroll
        for (int rh = 0; rh < 2; rh++) {
            float sv = 0.f, qv = 0.f;
#pragma unroll
            for (int nt = 0; nt < 8; nt++) {
                float x0 = acc[mt][nt][rh * 2]     + b1v[nt * 2];
                float x1 = acc[mt][nt][rh * 2 + 1] + b1v[nt * 2 + 1];
                acc[mt][nt][rh * 2] = x0; acc[mt][nt][rh * 2 + 1] = x1;
                sv += x0 + x1;
                qv += x0 * x0 + x1 * x1;
            }
            sv += __shfl_xor_sync(0xffffffffu, sv, 1);
            sv += __shfl_xor_sync(0xffffffffu, sv, 2);
            qv += __shfl_xor_sync(0xffffffffu, qv, 1);
            qv += __shfl_xor_sync(0xffffffffu, qv, 2);
            if ((lid & 3) == 0) {
                int rl = wr * 32 + mt * 16 + rh * 8 + (lid >> 2);
                pS[rl * 2 + wc] = sv;
                pQ[rl * 2 + wc] = qv;
            }
        }
    __syncthreads();   // partials visible; ALL warps past final mma -> buffers reusable

    // normalize + relu + pack fp16 -> H tiles in smem (overwrite GEMM1 buffers)
#pragma unroll
    for (int mt = 0; mt < 2; mt++)
#pragma unroll
        for (int rh = 0; rh < 2; rh++) {
            int rl = wr * 32 + mt * 16 + rh * 8 + (lid >> 2);
            float mu = (pS[rl * 2] + pS[rl * 2 + 1]) * 0.0078125f;
            float var = (pQ[rl * 2] + pQ[rl * 2 + 1]) * 0.0078125f - mu * mu;
            float rs = rsqrtf(var + 1e-5f);
#pragma unroll
            for (int nt = 0; nt < 8; nt++) {
                float v0 = fmaxf((acc[mt][nt][rh * 2]     - mu) * rs * gv[nt * 2]     + bev[nt * 2], 0.f);
                float v1 = fmaxf((acc[mt][nt][rh * 2 + 1] - mu) * rs * gv[nt * 2 + 1] + bev[nt * 2 + 1], 0.f);
                int col = wc * 64 + nt * 8 + 2 * (lid & 3);
                uint32_t off = (uint32_t)(col >> 5) * 8192 + SW64(rl * 64 + (col & 31) * 2);
                *(uint32_t*)(smc + off) = packh2(v0, v1);
            }
        }

    CPA_WAIT(0);
    __syncthreads();   // H + W2 resident

    // ---------------- GEMM2: 4 chunks, full N per warp-column ----------------
    float acc2[2][8][4];
#pragma unroll
    for (int a = 0; a < 2; a++)
#pragma unroll
        for (int b = 0; b < 8; b++)
#pragma unroll
            for (int c = 0; c < 4; c++) acc2[a][b][c] = 0.f;
#pragma unroll
    for (int ch = 0; ch < 4; ch++)
        mma_chunk32(sbase + ch * 8192, sbase + OFF_W2 + ch * 8192,
                    wr * 32, wc * 64, lid, acc2);

    // bias2
#pragma unroll
    for (int nt = 0; nt < 8; nt++) {
        float2 t = *(const float2*)(B2 + wc * 64 + nt * 8 + 2 * (lid & 3));
#pragma unroll
        for (int mt = 0; mt < 2; mt++) {
            acc2[mt][nt][0] += t.x; acc2[mt][nt][1] += t.y;
            acc2[mt][nt][2] += t.x; acc2[mt][nt][3] += t.y;
        }
    }

    // ---------------- epilogues ----------------
#pragma unroll
    for (int mt = 0; mt < 2; mt++)
#pragma unroll
        for (int rh = 0; rh < 2; rh++) {
            int rl = wr * 32 + mt * 16 + rh * 8 + (lid >> 2);
            int r  = row0 + rl;
            if constexpr (EPI == 0 || EPI == 3) {
                if (r < NN) {
                    float* dst = (EPI == 0) ? g_q : outp;
#pragma unroll
                    for (int nt = 0; nt < 8; nt++)
                        *(float2*)(dst + (size_t)r * 128 + wc * 64 + nt * 8 + 2 * (lid & 3)) =
                            make_float2(acc2[mt][nt][rh * 2], acc2[mt][nt][rh * 2 + 1]);
                }
            } else if constexpr (EPI == 1) {
                int d = ds[rl];
#pragma unroll
                for (int hl = 0; hl < 4; hl++) {
                    float part = 0.f;
#pragma unroll
                    for (int jj = 0; jj < 2; jj++) {
                        int nt = hl * 2 + jj;
                        float2 q2 = *(const float2*)(g_q + (size_t)d * 128 + wc * 64 + nt * 8 + 2 * (lid & 3));
                        part += acc2[mt][nt][rh * 2] * q2.x + acc2[mt][nt][rh * 2 + 1] * q2.y;
                    }
                    part += __shfl_xor_sync(0xffffffffu, part, 1);
                    part += __shfl_xor_sync(0xffffffffu, part, 2);
                    if ((lid & 3) == 0) {
                        int hd = wc * 4 + hl;
                        float lg = part * 0.25f;
                        g_logits[(size_t)r * 8 + hd] = lg;
                        atomicAdd(&g_den[d * 8 + hd], __expf(lg));
                    }
                }
            } else {  // EPI == 2
                int d = ds[rl];
                float eww = ew[r];
#pragma unroll
                for (int hl = 0; hl < 4; hl++) {
                    int hd = wc * 4 + hl;
                    float sc = __expf(g_logits[(size_t)r * 8 + hd]) / g_den[d * 8 + hd] * eww;
#pragma unroll
                    for (int jj = 0; jj < 2; jj++) {
                        int nt = hl * 2 + jj;
                        float* op = g_aggr + (size_t)d * 128 + wc * 64 + nt * 8 + 2 * (lid & 3);
                        asm volatile("red.global.add.v2.f32 [%0], {%1,%2};" ::
                            "l"(op), "f"(acc2[mt][nt][rh * 2] * sc),
                                     "f"(acc2[mt][nt][rh * 2 + 1] * sc) : "memory");
                    }
                }
            }
        }
}

extern "C" void kernel_launch(void* const* d_in, const int* in_sizes, int n_in,
                              void* d_out, int out_size)
{
    const float* hPtr = (const float*)d_in[0];
    const float* ef   = (const float*)d_in[1];
    const float* ew   = (const float*)d_in[2];
    const void*  eidx = (const void*)d_in[3];
    const float* hk[6], *hv[6], *hq[6], *no[6];
    for (int i = 0; i < 6; i++) {
        hk[i] = (const float*)d_in[4 + i];
        hv[i] = (const float*)d_in[10 + i];
        hq[i] = (const float*)d_in[16 + i];
        no[i] = (const float*)d_in[22 + i];
    }
    float* outp = (float*)d_out;

    cudaFuncSetAttribute(mlp_mma<4, 28, 0>, cudaFuncAttributeMaxDynamicSharedMemorySize, MLP_SMEM);
    cudaFuncSetAttribute(mlp_mma<10, 0, 1>, cudaFuncAttributeMaxDynamicSharedMemorySize, MLP_SMEM);
    cudaFuncSetAttribute(mlp_mma<10, 14, 2>, cudaFuncAttributeMaxDynamicSharedMemorySize, MLP_SMEM);
    cudaFuncSetAttribute(mlp_mma<8, 36, 3>, cudaFuncAttributeMaxDynamicSharedMemorySize, MLP_SMEM);

    const int nodeBlocks = (NN + 127) / 128;           // 391
    const int edgeBlocks = EE / 128;                   // 6250
    const int flatBlocks = (NN * 128 + 255) / 256;
    const int idxBlocks  = (EE + 255) / 256;
    const int prepBlocks = (EE * 64 / 8 + NN * 128 / 8 + 255) / 256;
    const int agBlocks   = (NN * 128 / 8 + 255) / 256;

    detect_idx_kernel<<<1, 32>>>((const unsigned*)eidx);
    convert_idx_kernel<<<idxBlocks, 256>>>(eidx);
    prep_w<<<96, 256>>>(hk[0], hk[4], hv[0], hv[4], hq[0], hq[4], no[0], no[4]);
    prep_in<<<prepBlocks, 256>>>(ef, hPtr);
    init_kernel<<<flatBlocks, 256>>>();

    // q = MLP_hq(h)
    mlp_mma<4, 28, 0><<<nodeBlocks, 256, MLP_SMEM>>>(
        nullptr, hq[1], hq[2], hq[3], hq[5], nullptr);

    // k-MLP + logits + den
    mlp_mma<10, 0, 1><<<edgeBlocks, 256, MLP_SMEM>>>(
        nullptr, hk[1], hk[2], hk[3], hk[5], nullptr);

    // v-MLP + alpha*e_w*v scatter
    mlp_mma<10, 14, 2><<<edgeBlocks, 256, MLP_SMEM>>>(
        ew, hv[1], hv[2], hv[3], hv[5], nullptr);

    // aggr -> fp16
    prep_ag<<<agBlocks, 256>>>();

    // out = MLP_no([aggr | h])
    mlp_mma<8, 36, 3><<<nodeBlocks, 256, MLP_SMEM>>>(
        nullptr, no[1], no[2], no[3], no[5], outp);
}